// round 1
// baseline (speedup 1.0000x reference)
#include <cuda_runtime.h>
#include <cuda_bf16.h>
#include <cstdint>

// Problem shape
#define B_  8
#define S1_ 2048
#define S2_ 2048
#define D_  512
#define F_  256

// Scratch: Q, K, V projections and attention output. 4 x 16MB.
__device__ float g_Q [B_ * S1_ * F_];
__device__ float g_K [B_ * S2_ * F_];
__device__ float g_V [B_ * S2_ * F_];
__device__ float g_AO[B_ * S1_ * F_];

// ---------------------------------------------------------------------------
// Tiled GEMM with bias: C[M,N] = A[M,KD] @ W[KD,N] + bias[N]
// 64x64 block tile, BK=16, 256 threads, 4x4 microtile per thread.
// ---------------------------------------------------------------------------
template<int KD>
__global__ void __launch_bounds__(256) gemm_bias_kernel(
    const float* __restrict__ A, const float* __restrict__ W,
    const float* __restrict__ bias, float* __restrict__ C, int N)
{
    __shared__ float As[16][68];   // [k][m], padded row (272B, 16B-aligned)
    __shared__ float Bs[16][68];   // [k][n]

    const int tid = threadIdx.x;
    const int tx = tid & 15;            // 0..15 -> n microtile
    const int ty = tid >> 4;            // 0..15 -> m microtile
    const int row0 = blockIdx.y * 64;
    const int col0 = blockIdx.x * 64;

    // A-tile load mapping: thread loads float4 at (am, ak..ak+3)
    const int am = tid >> 2;            // 0..63
    const int ak = (tid & 3) * 4;       // 0,4,8,12
    // W-tile load mapping: thread loads float4 at (wk, wn..wn+3)
    const int wk = tid >> 4;            // 0..15
    const int wn = (tid & 15) * 4;      // 0..60

    float acc[4][4];
    #pragma unroll
    for (int i = 0; i < 4; i++)
        #pragma unroll
        for (int j = 0; j < 4; j++) acc[i][j] = 0.f;

    for (int k0 = 0; k0 < KD; k0 += 16) {
        float4 av = *(const float4*)(A + (size_t)(row0 + am) * KD + k0 + ak);
        As[ak + 0][am] = av.x;
        As[ak + 1][am] = av.y;
        As[ak + 2][am] = av.z;
        As[ak + 3][am] = av.w;
        float4 wv = *(const float4*)(W + (size_t)(k0 + wk) * N + col0 + wn);
        *(float4*)&Bs[wk][wn] = wv;
        __syncthreads();

        #pragma unroll
        for (int kk = 0; kk < 16; kk++) {
            float4 a = *(const float4*)&As[kk][ty * 4];
            float4 b = *(const float4*)&Bs[kk][tx * 4];
            acc[0][0] += a.x * b.x; acc[0][1] += a.x * b.y; acc[0][2] += a.x * b.z; acc[0][3] += a.x * b.w;
            acc[1][0] += a.y * b.x; acc[1][1] += a.y * b.y; acc[1][2] += a.y * b.z; acc[1][3] += a.y * b.w;
            acc[2][0] += a.z * b.x; acc[2][1] += a.z * b.y; acc[2][2] += a.z * b.z; acc[2][3] += a.z * b.w;
            acc[3][0] += a.w * b.x; acc[3][1] += a.w * b.y; acc[3][2] += a.w * b.z; acc[3][3] += a.w * b.w;
        }
        __syncthreads();
    }

    float4 bv = *(const float4*)(bias + col0 + tx * 4);
    #pragma unroll
    for (int i = 0; i < 4; i++) {
        float4 o;
        o.x = acc[i][0] + bv.x;
        o.y = acc[i][1] + bv.y;
        o.z = acc[i][2] + bv.z;
        o.w = acc[i][3] + bv.w;
        *(float4*)(C + (size_t)(row0 + ty * 4 + i) * N + col0 + tx * 4) = o;
    }
}

// ---------------------------------------------------------------------------
// Flash attention: per CTA = (batch b, 32-query tile).
// Online softmax over 2048 keys in 32-key tiles. F=256, fp32.
// smem layout: Qs[32][256], Ks[32][256], Vs[32][256] (XOR chunk-swizzled),
//              Ss[32][33], mrow[32], lrow[32], srow[32].
// ---------------------------------------------------------------------------
#define BQ 32
#define BK 32
#define NCH (F_ / 4)   // 64 float4 chunks per row

__global__ void __launch_bounds__(256) attn_kernel(
    const float* __restrict__ Q, const float* __restrict__ Kg_,
    const float* __restrict__ Vg_, float* __restrict__ O)
{
    extern __shared__ float sm[];
    float* Qs   = sm;                      // 32*256
    float* Ks   = Qs + BQ * F_;            // 32*256
    float* Vs   = Ks + BK * F_;            // 32*256
    float* Ss   = Vs + BK * F_;            // 32*33
    float* mrow = Ss + BQ * 33;            // 32
    float* lrow = mrow + BQ;               // 32
    float* srow = lrow + BQ;               // 32

    const int b   = blockIdx.y;
    const int q0  = blockIdx.x * BQ;
    const int tid = threadIdx.x;

    const float* Qg = Q   + ((size_t)b * S1_ + q0) * F_;
    const float* Kg = Kg_ + (size_t)b * S2_ * F_;
    const float* Vg = Vg_ + (size_t)b * S2_ * F_;

    // Load Q tile, swizzle chunk by (row & 3)
    for (int i = tid; i < BQ * NCH; i += 256) {
        int row = i >> 6;          // /64
        int c   = i & 63;
        float4 v = *(const float4*)(Qg + row * F_ + c * 4);
        *(float4*)(Qs + row * F_ + ((c ^ (row & 3)) * 4)) = v;
    }

    const int q  = tid >> 3;           // query row this thread owns (0..31)
    const int m8 = tid & 7;            // lane-group within query
    const int kb = m8 * 4;             // base key col in S tile
    const float qsw = 0.f; (void)qsw;

    float acc[32];
    #pragma unroll
    for (int i = 0; i < 32; i++) acc[i] = 0.f;
    if (tid < BQ) { mrow[tid] = -1e30f; lrow[tid] = 0.f; }
    __syncthreads();

    const float scale = 0.0625f;  // 1/sqrt(256)

    for (int kt = 0; kt < S2_; kt += BK) {
        // --- load K and V tiles, swizzle chunk by (row >> 2) ---
        for (int i = tid; i < BK * NCH; i += 256) {
            int row = i >> 6;
            int c   = i & 63;
            int sc  = (c ^ (row >> 2)) * 4;
            float4 kv = *(const float4*)(Kg + (size_t)(kt + row) * F_ + c * 4);
            *(float4*)(Ks + row * F_ + sc) = kv;
            float4 vv = *(const float4*)(Vg + (size_t)(kt + row) * F_ + c * 4);
            *(float4*)(Vs + row * F_ + sc) = vv;
        }
        __syncthreads();

        // --- S = Q @ K^T : thread computes S[q][kb..kb+3] ---
        {
            float s0 = 0.f, s1 = 0.f, s2 = 0.f, s3 = 0.f;
            const float* Qrow = Qs + q * F_;
            const float* K0 = Ks + (kb + 0) * F_;
            const float* K1 = Ks + (kb + 1) * F_;
            const float* K2 = Ks + (kb + 2) * F_;
            const float* K3 = Ks + (kb + 3) * F_;
            const int qx = q & 3;
            const int kx = m8;   // (kb+j)>>2 == m8 for all j in 0..3
            #pragma unroll 8
            for (int c = 0; c < NCH; c++) {
                float4 qv = *(const float4*)(Qrow + ((c ^ qx) * 4));
                int ko = (c ^ kx) * 4;
                float4 k0 = *(const float4*)(K0 + ko);
                float4 k1 = *(const float4*)(K1 + ko);
                float4 k2 = *(const float4*)(K2 + ko);
                float4 k3 = *(const float4*)(K3 + ko);
                s0 += qv.x * k0.x + qv.y * k0.y + qv.z * k0.z + qv.w * k0.w;
                s1 += qv.x * k1.x + qv.y * k1.y + qv.z * k1.z + qv.w * k1.w;
                s2 += qv.x * k2.x + qv.y * k2.y + qv.z * k2.z + qv.w * k2.w;
                s3 += qv.x * k3.x + qv.y * k3.y + qv.z * k3.z + qv.w * k3.w;
            }
            Ss[q * 33 + kb + 0] = s0 * scale;
            Ss[q * 33 + kb + 1] = s1 * scale;
            Ss[q * 33 + kb + 2] = s2 * scale;
            Ss[q * 33 + kb + 3] = s3 * scale;
        }
        __syncthreads();

        // --- online softmax: one thread per query row ---
        if (tid < BQ) {
            float* row = Ss + tid * 33;
            float mold = mrow[tid];
            float mnew = mold;
            #pragma unroll
            for (int j = 0; j < BK; j++) mnew = fmaxf(mnew, row[j]);
            float sc = __expf(mold - mnew);
            float l = lrow[tid] * sc;
            #pragma unroll
            for (int j = 0; j < BK; j++) {
                float p = __expf(row[j] - mnew);
                row[j] = p;
                l += p;
            }
            mrow[tid] = mnew;
            lrow[tid] = l;
            srow[tid] = sc;
        }
        __syncthreads();

        // --- acc = acc*scale + P @ V ---
        {
            float sc = srow[q];
            #pragma unroll
            for (int i = 0; i < 32; i++) acc[i] *= sc;
            const float* Pr = Ss + q * 33;
            #pragma unroll 4
            for (int key = 0; key < BK; key++) {
                float p = Pr[key];
                const float* Vrow = Vs + key * F_;
                int sw = key >> 2;
                #pragma unroll
                for (int f4 = 0; f4 < 8; f4++) {
                    int c = m8 + f4 * 8;                  // chunk covering f = c*4
                    float4 v = *(const float4*)(Vrow + ((c ^ sw) * 4));
                    acc[f4 * 4 + 0] += p * v.x;
                    acc[f4 * 4 + 1] += p * v.y;
                    acc[f4 * 4 + 2] += p * v.z;
                    acc[f4 * 4 + 3] += p * v.w;
                }
            }
        }
        __syncthreads();
    }

    // --- write normalized output ---
    float inv = 1.f / lrow[q];
    float* Orow = O + ((size_t)b * S1_ + q0 + q) * F_;
    #pragma unroll
    for (int f4 = 0; f4 < 8; f4++) {
        float4 o;
        o.x = acc[f4 * 4 + 0] * inv;
        o.y = acc[f4 * 4 + 1] * inv;
        o.z = acc[f4 * 4 + 2] * inv;
        o.w = acc[f4 * 4 + 3] * inv;
        *(float4*)(Orow + m8 * 4 + f4 * 32) = o;
    }
}

// ---------------------------------------------------------------------------
// Launch
// ---------------------------------------------------------------------------
extern "C" void kernel_launch(void* const* d_in, const int* in_sizes, int n_in,
                              void* d_out, int out_size)
{
    const float* feat1 = (const float*)d_in[0];
    const float* feat2 = (const float*)d_in[1];
    const float* Wq    = (const float*)d_in[2];
    const float* bq    = (const float*)d_in[3];
    const float* Wk    = (const float*)d_in[4];
    const float* bk    = (const float*)d_in[5];
    const float* Wv    = (const float*)d_in[6];
    const float* bv    = (const float*)d_in[7];
    const float* Wfc   = (const float*)d_in[8];
    const float* bfc   = (const float*)d_in[9];
    float* out = (float*)d_out;

    float *gQ, *gK, *gV, *gAO;
    cudaGetSymbolAddress((void**)&gQ,  g_Q);
    cudaGetSymbolAddress((void**)&gK,  g_K);
    cudaGetSymbolAddress((void**)&gV,  g_V);
    cudaGetSymbolAddress((void**)&gAO, g_AO);

    const int M = B_ * S1_;                     // 16384
    dim3 gemm_grid(F_ / 64, M / 64);            // (4, 256)

    gemm_bias_kernel<D_><<<gemm_grid, 256>>>(feat1, Wq, bq, gQ, F_);
    gemm_bias_kernel<D_><<<gemm_grid, 256>>>(feat2, Wk, bk, gK, F_);
    gemm_bias_kernel<D_><<<gemm_grid, 256>>>(feat2, Wv, bv, gV, F_);

    size_t attn_smem = (size_t)(3 * BQ * F_ + BQ * 33 + 3 * BQ) * sizeof(float);
    cudaFuncSetAttribute(attn_kernel, cudaFuncAttributeMaxDynamicSharedMemorySize,
                         (int)attn_smem);
    dim3 attn_grid(S1_ / BQ, B_);               // (64, 8)
    attn_kernel<<<attn_grid, 256, attn_smem>>>(gQ, gK, gV, gAO);

    gemm_bias_kernel<F_><<<gemm_grid, 256>>>(gAO, Wfc, bfc, out, F_);
}

// round 2
// speedup vs baseline: 1.8704x; 1.8704x over previous
#include <cuda_runtime.h>
#include <cuda_bf16.h>
#include <cstdint>

// Problem shape
#define B_  8
#define S1_ 2048
#define S2_ 2048
#define D_  512
#define F_  256

// Scratch: Q, K, V projections and attention output. 4 x 16MB.
__device__ float g_Q [B_ * S1_ * F_];
__device__ float g_K [B_ * S2_ * F_];
__device__ float g_V [B_ * S2_ * F_];
__device__ float g_AO[B_ * S1_ * F_];

// ---------------------------------------------------------------------------
// Tiled GEMM with bias: C[M,N] = A[M,KD] @ W[KD,N] + bias[N]
// 64x64 block tile, BK=16, 256 threads, 4x4 microtile per thread.
// (Already at fp32 FFMA roofline — unchanged.)
// ---------------------------------------------------------------------------
template<int KD>
__global__ void __launch_bounds__(256) gemm_bias_kernel(
    const float* __restrict__ A, const float* __restrict__ W,
    const float* __restrict__ bias, float* __restrict__ C, int N)
{
    __shared__ float As[16][68];
    __shared__ float Bs[16][68];

    const int tid = threadIdx.x;
    const int tx = tid & 15;
    const int ty = tid >> 4;
    const int row0 = blockIdx.y * 64;
    const int col0 = blockIdx.x * 64;

    const int am = tid >> 2;
    const int ak = (tid & 3) * 4;
    const int wk = tid >> 4;
    const int wn = (tid & 15) * 4;

    float acc[4][4];
    #pragma unroll
    for (int i = 0; i < 4; i++)
        #pragma unroll
        for (int j = 0; j < 4; j++) acc[i][j] = 0.f;

    for (int k0 = 0; k0 < KD; k0 += 16) {
        float4 av = *(const float4*)(A + (size_t)(row0 + am) * KD + k0 + ak);
        As[ak + 0][am] = av.x;
        As[ak + 1][am] = av.y;
        As[ak + 2][am] = av.z;
        As[ak + 3][am] = av.w;
        float4 wv = *(const float4*)(W + (size_t)(k0 + wk) * N + col0 + wn);
        *(float4*)&Bs[wk][wn] = wv;
        __syncthreads();

        #pragma unroll
        for (int kk = 0; kk < 16; kk++) {
            float4 a = *(const float4*)&As[kk][ty * 4];
            float4 b = *(const float4*)&Bs[kk][tx * 4];
            acc[0][0] += a.x * b.x; acc[0][1] += a.x * b.y; acc[0][2] += a.x * b.z; acc[0][3] += a.x * b.w;
            acc[1][0] += a.y * b.x; acc[1][1] += a.y * b.y; acc[1][2] += a.y * b.z; acc[1][3] += a.y * b.w;
            acc[2][0] += a.z * b.x; acc[2][1] += a.z * b.y; acc[2][2] += a.z * b.z; acc[2][3] += a.z * b.w;
            acc[3][0] += a.w * b.x; acc[3][1] += a.w * b.y; acc[3][2] += a.w * b.z; acc[3][3] += a.w * b.w;
        }
        __syncthreads();
    }

    float4 bv = *(const float4*)(bias + col0 + tx * 4);
    #pragma unroll
    for (int i = 0; i < 4; i++) {
        float4 o;
        o.x = acc[i][0] + bv.x;
        o.y = acc[i][1] + bv.y;
        o.z = acc[i][2] + bv.z;
        o.w = acc[i][3] + bv.w;
        *(float4*)(C + (size_t)(row0 + ty * 4 + i) * N + col0 + tx * 4) = o;
    }
}

// ---------------------------------------------------------------------------
// Flash attention v2: BQ=64, BK=64, register-blocked GEMMs inside the loop.
//   QK^T: 4x4 microtile, K rows XOR-chunk-swizzled -> conflict-free, 2 B/FMA
//   PV:   4q x 16f microtile, 1.25 B/FMA
//   softmax: 4 lanes per row + butterfly shuffles
// smem: Qs[64][256] + Ks[64][256](swz) + Vs[64][256] + Ps[64][68] + aux ~210KB
// ---------------------------------------------------------------------------
#define BQ 64
#define BK 64

__global__ void __launch_bounds__(256, 1) attn_kernel(
    const float* __restrict__ Q, const float* __restrict__ Kg_,
    const float* __restrict__ Vg_, float* __restrict__ O)
{
    extern __shared__ float sm[];
    float* Qs   = sm;                       // 64*256
    float* Ks   = Qs + BQ * F_;             // 64*256 (chunk-swizzled)
    float* Vs   = Ks + BK * F_;             // 64*256
    float* Ps   = Vs + BK * F_;             // 64*68
    float* mrow = Ps + BQ * 68;             // 64
    float* lrow = mrow + BQ;                // 64
    float* srow = lrow + BQ;                // 64

    const int b   = blockIdx.y;
    const int q0  = blockIdx.x * BQ;
    const int tid = threadIdx.x;

    const float* Qg = Q   + ((size_t)b * S1_ + q0) * F_;
    const float* Kg = Kg_ + (size_t)b * S2_ * F_;
    const float* Vg = Vg_ + (size_t)b * S2_ * F_;

    // Load Q tile (plain layout; reads are broadcasts)
    #pragma unroll
    for (int l = 0; l < 16; l++) {
        int lin = l * 256 + tid;
        int row = lin >> 6;
        int c   = lin & 63;
        float4 v = *(const float4*)(Qg + row * F_ + c * 4);
        *(float4*)(Qs + row * F_ + c * 4) = v;
    }
    if (tid < BQ) { mrow[tid] = -1e30f; lrow[tid] = 0.f; }

    const int ty = tid >> 4;    // 0..15 -> 4 query rows each
    const int tx = tid & 15;    // 0..15 -> 4 key cols (S) / 16 f cols (PV)
    const int kxor = tx & 7;    // K swizzle term for rows tx*4+j (row>>2 == tx)

    float acc[4][16];
    #pragma unroll
    for (int i = 0; i < 4; i++)
        #pragma unroll
        for (int j = 0; j < 16; j++) acc[i][j] = 0.f;

    const float scale = 0.0625f;  // 1/sqrt(256)
    __syncthreads();

    for (int kt = 0; kt < S2_; kt += BK) {
        // ---- load K (swizzled) and V tiles ----
        #pragma unroll
        for (int l = 0; l < 16; l++) {
            int lin = l * 256 + tid;
            int row = lin >> 6;
            int c   = lin & 63;
            float4 kv = *(const float4*)(Kg + (size_t)(kt + row) * F_ + c * 4);
            int cs = c ^ ((row >> 2) & 7);
            *(float4*)(Ks + row * F_ + cs * 4) = kv;
            float4 vv = *(const float4*)(Vg + (size_t)(kt + row) * F_ + c * 4);
            *(float4*)(Vs + row * F_ + c * 4) = vv;
        }
        __syncthreads();

        // ---- S = Q @ K^T : 64x64, 4x4 microtile per thread ----
        {
            float s[4][4];
            #pragma unroll
            for (int i = 0; i < 4; i++)
                #pragma unroll
                for (int j = 0; j < 4; j++) s[i][j] = 0.f;

            const float* Qb = Qs + (ty * 4) * F_;
            const float* Kb = Ks + (tx * 4) * F_;
            #pragma unroll 8
            for (int c = 0; c < 64; c++) {
                float4 qv[4], kv[4];
                #pragma unroll
                for (int i = 0; i < 4; i++)
                    qv[i] = *(const float4*)(Qb + i * F_ + c * 4);
                int ko = (c ^ kxor) * 4;
                #pragma unroll
                for (int j = 0; j < 4; j++)
                    kv[j] = *(const float4*)(Kb + j * F_ + ko);
                #pragma unroll
                for (int i = 0; i < 4; i++)
                    #pragma unroll
                    for (int j = 0; j < 4; j++)
                        s[i][j] += qv[i].x * kv[j].x + qv[i].y * kv[j].y
                                 + qv[i].z * kv[j].z + qv[i].w * kv[j].w;
            }
            #pragma unroll
            for (int i = 0; i < 4; i++) {
                float4 o;
                o.x = s[i][0] * scale; o.y = s[i][1] * scale;
                o.z = s[i][2] * scale; o.w = s[i][3] * scale;
                *(float4*)(Ps + (ty * 4 + i) * 68 + tx * 4) = o;
            }
        }
        __syncthreads();

        // ---- online softmax: 4 lanes per row ----
        {
            int r   = tid >> 2;
            int seg = tid & 3;
            float* row = Ps + r * 68 + seg * 16;
            float v[16];
            float mx = -1e30f;
            #pragma unroll
            for (int j = 0; j < 16; j++) { v[j] = row[j]; mx = fmaxf(mx, v[j]); }
            mx = fmaxf(mx, __shfl_xor_sync(0xffffffffu, mx, 1));
            mx = fmaxf(mx, __shfl_xor_sync(0xffffffffu, mx, 2));
            float mold = mrow[r];
            float mnew = fmaxf(mold, mx);
            float sum = 0.f;
            #pragma unroll
            for (int j = 0; j < 16; j++) {
                float e = __expf(v[j] - mnew);
                row[j] = e;
                sum += e;
            }
            sum += __shfl_xor_sync(0xffffffffu, sum, 1);
            sum += __shfl_xor_sync(0xffffffffu, sum, 2);
            if (seg == 0) {
                float scf = __expf(mold - mnew);
                srow[r] = scf;
                lrow[r] = lrow[r] * scf + sum;
                mrow[r] = mnew;
            }
        }
        __syncthreads();

        // ---- acc = acc*scf + P @ V : 4q x 16f microtile ----
        {
            #pragma unroll
            for (int i = 0; i < 4; i++) {
                float scf = srow[ty * 4 + i];
                #pragma unroll
                for (int j = 0; j < 16; j++) acc[i][j] *= scf;
            }
            const float* Pb = Ps + (ty * 4) * 68;
            #pragma unroll 4
            for (int key = 0; key < BK; key++) {
                float p[4];
                #pragma unroll
                for (int i = 0; i < 4; i++) p[i] = Pb[i * 68 + key];
                float4 vv[4];
                #pragma unroll
                for (int j = 0; j < 4; j++)
                    vv[j] = *(const float4*)(Vs + key * F_ + (tx + 16 * j) * 4);
                #pragma unroll
                for (int i = 0; i < 4; i++) {
                    #pragma unroll
                    for (int j = 0; j < 4; j++) {
                        acc[i][j * 4 + 0] += p[i] * vv[j].x;
                        acc[i][j * 4 + 1] += p[i] * vv[j].y;
                        acc[i][j * 4 + 2] += p[i] * vv[j].z;
                        acc[i][j * 4 + 3] += p[i] * vv[j].w;
                    }
                }
            }
        }
        __syncthreads();
    }

    // ---- write normalized output ----
    #pragma unroll
    for (int i = 0; i < 4; i++) {
        float inv = 1.f / lrow[ty * 4 + i];
        float* Orow = O + ((size_t)b * S1_ + q0 + ty * 4 + i) * F_;
        #pragma unroll
        for (int j = 0; j < 4; j++) {
            float4 o;
            o.x = acc[i][j * 4 + 0] * inv;
            o.y = acc[i][j * 4 + 1] * inv;
            o.z = acc[i][j * 4 + 2] * inv;
            o.w = acc[i][j * 4 + 3] * inv;
            *(float4*)(Orow + (tx + 16 * j) * 4) = o;
        }
    }
}

// ---------------------------------------------------------------------------
// Launch
// ---------------------------------------------------------------------------
extern "C" void kernel_launch(void* const* d_in, const int* in_sizes, int n_in,
                              void* d_out, int out_size)
{
    const float* feat1 = (const float*)d_in[0];
    const float* feat2 = (const float*)d_in[1];
    const float* Wq    = (const float*)d_in[2];
    const float* bq    = (const float*)d_in[3];
    const float* Wk    = (const float*)d_in[4];
    const float* bk    = (const float*)d_in[5];
    const float* Wv    = (const float*)d_in[6];
    const float* bv    = (const float*)d_in[7];
    const float* Wfc   = (const float*)d_in[8];
    const float* bfc   = (const float*)d_in[9];
    float* out = (float*)d_out;

    float *gQ, *gK, *gV, *gAO;
    cudaGetSymbolAddress((void**)&gQ,  g_Q);
    cudaGetSymbolAddress((void**)&gK,  g_K);
    cudaGetSymbolAddress((void**)&gV,  g_V);
    cudaGetSymbolAddress((void**)&gAO, g_AO);

    const int M = B_ * S1_;                     // 16384
    dim3 gemm_grid(F_ / 64, M / 64);            // (4, 256)

    gemm_bias_kernel<D_><<<gemm_grid, 256>>>(feat1, Wq, bq, gQ, F_);
    gemm_bias_kernel<D_><<<gemm_grid, 256>>>(feat2, Wk, bk, gK, F_);
    gemm_bias_kernel<D_><<<gemm_grid, 256>>>(feat2, Wv, bv, gV, F_);

    size_t attn_smem = (size_t)(3 * BQ * F_ + BQ * 68 + 3 * BQ) * sizeof(float);
    cudaFuncSetAttribute(attn_kernel, cudaFuncAttributeMaxDynamicSharedMemorySize,
                         (int)attn_smem);
    dim3 attn_grid(S1_ / BQ, B_);               // (32, 8)
    attn_kernel<<<attn_grid, 256, attn_smem>>>(gQ, gK, gV, gAO);

    gemm_bias_kernel<F_><<<gemm_grid, 256>>>(gAO, Wfc, bfc, out, F_);
}

// round 4
// speedup vs baseline: 3.1055x; 1.6603x over previous
#include <cuda_runtime.h>
#include <cuda_bf16.h>
#include <cstdint>

// Problem shape
#define B_  8
#define S1_ 2048
#define S2_ 2048
#define D_  512
#define F_  256

// Scratch: split-bf16 Q/K, transposed split-bf16 V, fp32 attention output.
#define NQKV (B_ * S1_ * F_)
__device__ __align__(16) __nv_bfloat16 g_Qh [NQKV];
__device__ __align__(16) __nv_bfloat16 g_Ql [NQKV];
__device__ __align__(16) __nv_bfloat16 g_Kh [NQKV];
__device__ __align__(16) __nv_bfloat16 g_Kl [NQKV];
__device__ __align__(16) __nv_bfloat16 g_VTh[NQKV];   // [b, f, t]
__device__ __align__(16) __nv_bfloat16 g_VTl[NQKV];   // [b, f, t]
__device__ __align__(16) float         g_AO [NQKV];

// ===========================================================================
// Warp-MMA helpers (baseline PTX, valid for compute_103)
// ===========================================================================
__device__ __forceinline__ uint32_t smem_to_u32(const void* p) {
    uint32_t a;
    asm("{ .reg .u64 t; cvta.to.shared.u64 t, %1; cvt.u32.u64 %0, t; }"
        : "=r"(a) : "l"(p));
    return a;
}

__device__ __forceinline__ void ldsm4(uint32_t& r0, uint32_t& r1,
                                      uint32_t& r2, uint32_t& r3, uint32_t addr) {
    asm volatile("ldmatrix.sync.aligned.m8n8.x4.shared.b16 {%0,%1,%2,%3}, [%4];"
        : "=r"(r0), "=r"(r1), "=r"(r2), "=r"(r3) : "r"(addr));
}

__device__ __forceinline__ void mma_bf16(float (&d)[4], const uint32_t (&a)[4],
                                         uint32_t b0, uint32_t b1) {
    asm volatile(
        "mma.sync.aligned.m16n8k16.row.col.f32.bf16.bf16.f32 "
        "{%0,%1,%2,%3}, {%4,%5,%6,%7}, {%8,%9}, {%0,%1,%2,%3};"
        : "+f"(d[0]), "+f"(d[1]), "+f"(d[2]), "+f"(d[3])
        : "r"(a[0]), "r"(a[1]), "r"(a[2]), "r"(a[3]), "r"(b0), "r"(b1));
}

__device__ __forceinline__ void split_bf16(float x, __nv_bfloat16& h, __nv_bfloat16& l) {
    h = __float2bfloat16(x);
    l = __float2bfloat16(x - __bfloat162float(h));
}
__device__ __forceinline__ uint32_t pack2(__nv_bfloat16 a, __nv_bfloat16 b) {
    return (uint32_t)__bfloat16_as_ushort(a) | ((uint32_t)__bfloat16_as_ushort(b) << 16);
}

// ===========================================================================
// Tiled SIMT GEMM with bias. MODE 0: fp32 out. MODE 1: split-bf16 hi/lo out
// (row-major). MODE 2: split-bf16 hi/lo out, transposed [b, f, t].
// ===========================================================================
template<int KD, int MODE>
__global__ void __launch_bounds__(256) gemm_bias_kernel(
    const float* __restrict__ A, const float* __restrict__ W,
    const float* __restrict__ bias, float* __restrict__ Cf,
    __nv_bfloat16* __restrict__ Oh, __nv_bfloat16* __restrict__ Ol, int N)
{
    __shared__ float As[16][68];
    __shared__ float Bs[16][68];

    const int tid = threadIdx.x;
    const int tx = tid & 15;
    const int ty = tid >> 4;
    const int row0 = blockIdx.y * 64;
    const int col0 = blockIdx.x * 64;

    const int am = tid >> 2;
    const int ak = (tid & 3) * 4;
    const int wk = tid >> 4;
    const int wn = (tid & 15) * 4;

    float acc[4][4];
    #pragma unroll
    for (int i = 0; i < 4; i++)
        #pragma unroll
        for (int j = 0; j < 4; j++) acc[i][j] = 0.f;

    for (int k0 = 0; k0 < KD; k0 += 16) {
        float4 av = *(const float4*)(A + (size_t)(row0 + am) * KD + k0 + ak);
        As[ak + 0][am] = av.x;
        As[ak + 1][am] = av.y;
        As[ak + 2][am] = av.z;
        As[ak + 3][am] = av.w;
        float4 wv = *(const float4*)(W + (size_t)(k0 + wk) * N + col0 + wn);
        *(float4*)&Bs[wk][wn] = wv;
        __syncthreads();

        #pragma unroll
        for (int kk = 0; kk < 16; kk++) {
            float4 a = *(const float4*)&As[kk][ty * 4];
            float4 b = *(const float4*)&Bs[kk][tx * 4];
            acc[0][0] += a.x * b.x; acc[0][1] += a.x * b.y; acc[0][2] += a.x * b.z; acc[0][3] += a.x * b.w;
            acc[1][0] += a.y * b.x; acc[1][1] += a.y * b.y; acc[1][2] += a.y * b.z; acc[1][3] += a.y * b.w;
            acc[2][0] += a.z * b.x; acc[2][1] += a.z * b.y; acc[2][2] += a.z * b.z; acc[2][3] += a.z * b.w;
            acc[3][0] += a.w * b.x; acc[3][1] += a.w * b.y; acc[3][2] += a.w * b.z; acc[3][3] += a.w * b.w;
        }
        __syncthreads();
    }

    float4 bv = *(const float4*)(bias + col0 + tx * 4);
    float bvv[4] = {bv.x, bv.y, bv.z, bv.w};

    if (MODE == 0) {
        #pragma unroll
        for (int i = 0; i < 4; i++) {
            float4 o;
            o.x = acc[i][0] + bvv[0];
            o.y = acc[i][1] + bvv[1];
            o.z = acc[i][2] + bvv[2];
            o.w = acc[i][3] + bvv[3];
            *(float4*)(Cf + (size_t)(row0 + ty * 4 + i) * N + col0 + tx * 4) = o;
        }
    } else if (MODE == 1) {
        #pragma unroll
        for (int i = 0; i < 4; i++) {
            __nv_bfloat16 h[4], l[4];
            #pragma unroll
            for (int j = 0; j < 4; j++) split_bf16(acc[i][j] + bvv[j], h[j], l[j]);
            size_t base = (size_t)(row0 + ty * 4 + i) * N + col0 + tx * 4;
            *(uint32_t*)(Oh + base)     = pack2(h[0], h[1]);
            *(uint32_t*)(Oh + base + 2) = pack2(h[2], h[3]);
            *(uint32_t*)(Ol + base)     = pack2(l[0], l[1]);
            *(uint32_t*)(Ol + base + 2) = pack2(l[2], l[3]);
        }
    } else {
        const int b  = row0 >> 11;              // 2048 rows per batch
        const int t0 = (row0 & 2047) + ty * 4;
        #pragma unroll
        for (int j = 0; j < 4; j++) {
            const int f = col0 + tx * 4 + j;
            __nv_bfloat16 h[4], l[4];
            #pragma unroll
            for (int i = 0; i < 4; i++) split_bf16(acc[i][j] + bvv[j], h[i], l[i]);
            size_t base = ((size_t)(b * F_ + f)) * S2_ + t0;
            *(uint32_t*)(Oh + base)     = pack2(h[0], h[1]);
            *(uint32_t*)(Oh + base + 2) = pack2(h[2], h[3]);
            *(uint32_t*)(Ol + base)     = pack2(l[0], l[1]);
            *(uint32_t*)(Ol + base + 2) = pack2(l[2], l[3]);
        }
    }
}

// ===========================================================================
// HMMA flash attention (mma.sync m16n8k16 bf16, split hi/lo, no online max).
// CTA = 64 queries, 8 warps, 32 key tiles of 64.
//  S phase : warp = (qgroup 0-3) x (key-half 0-1): S[16q, 32k], 3 chains.
//  PV phase: warp = (qgroup 0-3) x (f-half 0-1):  O[16q, 128f] += P @ V.
// SMEM (bytes): QH 0, QL 32K, KH 64K, KL 96K, VH 128K, VL 160K,
//               PH 192K, PL 200K, L 208K. Total ~208.5KB, 1 CTA/SM.
// ===========================================================================
#define BQA 64
#define BKA 64
#define NKT (S2_ / BKA)

#define QH_OFF 0
#define QL_OFF 32768
#define KH_OFF 65536
#define KL_OFF 98304
#define VH_OFF 131072
#define VL_OFF 163840
#define PH_OFF 196608
#define PL_OFF 204800
#define L_OFF  212992
#define ATTN_SMEM_BYTES (212992 + 512)

__global__ void __launch_bounds__(256, 1) attn_kernel(
    const __nv_bfloat16* __restrict__ Qh, const __nv_bfloat16* __restrict__ Ql,
    const __nv_bfloat16* __restrict__ Kh, const __nv_bfloat16* __restrict__ Kl,
    const __nv_bfloat16* __restrict__ VTh, const __nv_bfloat16* __restrict__ VTl,
    float* __restrict__ AO)
{
    extern __shared__ char sm[];
    const uint32_t smb = smem_to_u32(sm);
    const int tid  = threadIdx.x;
    const int wid  = tid >> 5;
    const int lane = tid & 31;
    const int b    = blockIdx.y;
    const int q0   = blockIdx.x * BQA;
    const int qg   = wid & 3;     // query group (16 rows)
    const int kh   = wid >> 2;    // S: key half; PV: f half

    const __nv_bfloat16* Khb = Kh  + (size_t)b * S2_ * F_;
    const __nv_bfloat16* Klb = Kl  + (size_t)b * S2_ * F_;
    const __nv_bfloat16* Vhb = VTh + (size_t)b * F_ * S2_;
    const __nv_bfloat16* Vlb = VTl + (size_t)b * F_ * S2_;

    // ---- load Q tile (64 x 256 bf16, hi+lo), swizzled ----
    #pragma unroll
    for (int l = 0; l < 8; l++) {
        int id = l * 256 + tid;
        int r = id >> 5, c = id & 31;
        uint32_t off = r * 512 + ((c ^ (r & 7)) << 4);
        *(uint4*)(sm + QH_OFF + off) =
            *(const uint4*)(Qh + ((size_t)(b * S1_ + q0 + r)) * F_ + c * 8);
        *(uint4*)(sm + QL_OFF + off) =
            *(const uint4*)(Ql + ((size_t)(b * S1_ + q0 + r)) * F_ + c * 8);
    }

    // ---- per-lane fragment address bases ----
    // A-frag (Q / P): row = qg*16 + (lane&15), chunk-half = lane>>4
    const int arow = qg * 16 + (lane & 15);
    const int as   = arow & 7;
    const int ah   = lane >> 4;
    const uint32_t qbH = smb + QH_OFF + arow * 512;
    const uint32_t qbL = smb + QL_OFF + arow * 512;
    const uint32_t pbH = smb + PH_OFF + arow * 128;
    const uint32_t pbL = smb + PL_OFF + arow * 128;
    // B-frag (K / V): row = base + ((lane>>4)<<3) + (lane&7), chunk-half = (lane>>3)&1
    const int brow = ((lane >> 4) << 3) + (lane & 7);
    const int bs   = lane & 7;
    const int bh2  = (lane >> 3) & 1;
    const uint32_t kbH = smb + KH_OFF + (kh * 32 + brow) * 512;
    const uint32_t kbL = smb + KL_OFF + (kh * 32 + brow) * 512;
    const uint32_t vbH = smb + VH_OFF + (kh * 128 + brow) * 128;
    const uint32_t vbL = smb + VL_OFF + (kh * 128 + brow) * 128;
    // C-frag rows (for softmax / P store / output)
    const int crow  = qg * 16 + (lane >> 2);
    const int lq    = lane & 3;

    float accO[16][4];
    #pragma unroll
    for (int i = 0; i < 16; i++)
        #pragma unroll
        for (int j = 0; j < 4; j++) accO[i][j] = 0.f;
    float lsum0 = 0.f, lsum1 = 0.f;

    const float scale = 0.0625f;  // 1/sqrt(256)

    for (int it = 0; it < NKT; it++) {
        const int kt = it * BKA;
        __syncthreads();   // prev PV done before K/V overwrite

        // ---- load K (64x256) and VT (256x64) split tiles, swizzled ----
        #pragma unroll
        for (int l = 0; l < 8; l++) {
            int id = l * 256 + tid;
            int r = id >> 5, c = id & 31;
            uint32_t off = r * 512 + ((c ^ (r & 7)) << 4);
            *(uint4*)(sm + KH_OFF + off) =
                *(const uint4*)(Khb + (size_t)(kt + r) * F_ + c * 8);
            *(uint4*)(sm + KL_OFF + off) =
                *(const uint4*)(Klb + (size_t)(kt + r) * F_ + c * 8);
        }
        #pragma unroll
        for (int l = 0; l < 8; l++) {
            int id = l * 256 + tid;
            int r = id >> 3, c = id & 7;
            uint32_t off = r * 128 + ((c ^ (r & 7)) << 4);
            *(uint4*)(sm + VH_OFF + off) =
                *(const uint4*)(Vhb + (size_t)r * S2_ + kt + c * 8);
            *(uint4*)(sm + VL_OFF + off) =
                *(const uint4*)(Vlb + (size_t)r * S2_ + kt + c * 8);
        }
        __syncthreads();

        // ---- S = Qh@Kh + Qh@Kl + Ql@Kh  (warp: 16q x 32k) ----
        float sa[4][4];
        #pragma unroll
        for (int i = 0; i < 4; i++)
            #pragma unroll
            for (int j = 0; j < 4; j++) sa[i][j] = 0.f;

        #pragma unroll 4
        for (int ks = 0; ks < 16; ks++) {
            uint32_t aq[4], al[4], bhf[8], blf[8];
            uint32_t qc = (uint32_t)(((2 * ks + ah) ^ as) << 4);
            ldsm4(aq[0], aq[1], aq[2], aq[3], qbH + qc);
            ldsm4(al[0], al[1], al[2], al[3], qbL + qc);
            uint32_t kc = (uint32_t)(((2 * ks + bh2) ^ bs) << 4);
            ldsm4(bhf[0], bhf[1], bhf[2], bhf[3], kbH + kc);
            ldsm4(bhf[4], bhf[5], bhf[6], bhf[7], kbH + 16 * 512 + kc);
            ldsm4(blf[0], blf[1], blf[2], blf[3], kbL + kc);
            ldsm4(blf[4], blf[5], blf[6], blf[7], kbL + 16 * 512 + kc);
            #pragma unroll
            for (int nt = 0; nt < 4; nt++) {
                mma_bf16(sa[nt], aq, bhf[2 * nt], bhf[2 * nt + 1]);
                mma_bf16(sa[nt], aq, blf[2 * nt], blf[2 * nt + 1]);
                mma_bf16(sa[nt], al, bhf[2 * nt], bhf[2 * nt + 1]);
            }
        }

        // ---- softmax (no max-sub), split to bf16, store P hi/lo ----
        {
            const int rA = crow, rB = crow + 8;
            #pragma unroll
            for (int nt = 0; nt < 4; nt++) {
                float p0 = __expf(sa[nt][0] * scale);
                float p1 = __expf(sa[nt][1] * scale);
                float p2 = __expf(sa[nt][2] * scale);
                float p3 = __expf(sa[nt][3] * scale);
                lsum0 += p0 + p1;
                lsum1 += p2 + p3;
                int chunk = kh * 4 + nt;
                uint32_t offA = (uint32_t)(rA * 128 + ((chunk ^ (rA & 7)) << 4) + lq * 4);
                uint32_t offB = (uint32_t)(rB * 128 + ((chunk ^ (rB & 7)) << 4) + lq * 4);
                __nv_bfloat16 h0, l0, h1, l1, h2, l2, h3, l3;
                split_bf16(p0, h0, l0); split_bf16(p1, h1, l1);
                split_bf16(p2, h2, l2); split_bf16(p3, h3, l3);
                *(uint32_t*)(sm + PH_OFF + offA) = pack2(h0, h1);
                *(uint32_t*)(sm + PH_OFF + offB) = pack2(h2, h3);
                *(uint32_t*)(sm + PL_OFF + offA) = pack2(l0, l1);
                *(uint32_t*)(sm + PL_OFF + offB) = pack2(l2, l3);
            }
        }
        __syncthreads();

        // ---- O += Ph@Vh + Ph@Vl + Pl@Vh  (warp: 16q x 128f) ----
        {
            uint32_t pf[4][4], plf[4][4];
            #pragma unroll
            for (int ks = 0; ks < 4; ks++) {
                uint32_t pc = (uint32_t)(((2 * ks + ah) ^ as) << 4);
                ldsm4(pf[ks][0], pf[ks][1], pf[ks][2], pf[ks][3], pbH + pc);
                ldsm4(plf[ks][0], plf[ks][1], plf[ks][2], plf[ks][3], pbL + pc);
            }
            #pragma unroll 2
            for (int np = 0; np < 8; np++) {
                #pragma unroll
                for (int ks = 0; ks < 4; ks++) {
                    uint32_t vh[4], vl[4];
                    uint32_t off = (uint32_t)(np * 16 * 128 + (((2 * ks + bh2) ^ bs) << 4));
                    ldsm4(vh[0], vh[1], vh[2], vh[3], vbH + off);
                    ldsm4(vl[0], vl[1], vl[2], vl[3], vbL + off);
                    const int n0 = np * 2, n1 = np * 2 + 1;
                    mma_bf16(accO[n0], pf[ks],  vh[0], vh[1]);
                    mma_bf16(accO[n0], pf[ks],  vl[0], vl[1]);
                    mma_bf16(accO[n0], plf[ks], vh[0], vh[1]);
                    mma_bf16(accO[n1], pf[ks],  vh[2], vh[3]);
                    mma_bf16(accO[n1], pf[ks],  vl[2], vl[3]);
                    mma_bf16(accO[n1], plf[ks], vh[2], vh[3]);
                }
            }
        }
    }

    // ---- reduce l across lanes + key-halves ----
    float* lsm = (float*)(sm + L_OFF);
    lsum0 += __shfl_xor_sync(0xffffffffu, lsum0, 1);
    lsum0 += __shfl_xor_sync(0xffffffffu, lsum0, 2);
    lsum1 += __shfl_xor_sync(0xffffffffu, lsum1, 1);
    lsum1 += __shfl_xor_sync(0xffffffffu, lsum1, 2);
    __syncthreads();
    if (lq == 0) {
        lsm[kh * 64 + crow]     = lsum0;
        lsm[kh * 64 + crow + 8] = lsum1;
    }
    __syncthreads();

    // ---- normalize + store fp32 output ----
    const float inv0 = 1.f / (lsm[crow]     + lsm[64 + crow]);
    const float inv1 = 1.f / (lsm[crow + 8] + lsm[64 + crow + 8]);
    float* dst0 = AO + ((size_t)(b * S1_ + q0 + crow)) * F_;
    float* dst1 = AO + ((size_t)(b * S1_ + q0 + crow + 8)) * F_;
    #pragma unroll
    for (int nt = 0; nt < 16; nt++) {
        int col = kh * 128 + nt * 8 + 2 * lq;
        float2 o0 = make_float2(accO[nt][0] * inv0, accO[nt][1] * inv0);
        float2 o1 = make_float2(accO[nt][2] * inv1, accO[nt][3] * inv1);
        *(float2*)(dst0 + col) = o0;
        *(float2*)(dst1 + col) = o1;
    }
}

// ===========================================================================
// Launch
// ===========================================================================
extern "C" void kernel_launch(void* const* d_in, const int* in_sizes, int n_in,
                              void* d_out, int out_size)
{
    const float* feat1 = (const float*)d_in[0];
    const float* feat2 = (const float*)d_in[1];
    const float* Wq    = (const float*)d_in[2];
    const float* bq    = (const float*)d_in[3];
    const float* Wk    = (const float*)d_in[4];
    const float* bk    = (const float*)d_in[5];
    const float* Wv    = (const float*)d_in[6];
    const float* bv    = (const float*)d_in[7];
    const float* Wfc   = (const float*)d_in[8];
    const float* bfc   = (const float*)d_in[9];
    float* out = (float*)d_out;

    __nv_bfloat16 *gQh, *gQl, *gKh, *gKl, *gVTh, *gVTl;
    float* gAO;
    cudaGetSymbolAddress((void**)&gQh,  g_Qh);
    cudaGetSymbolAddress((void**)&gQl,  g_Ql);
    cudaGetSymbolAddress((void**)&gKh,  g_Kh);
    cudaGetSymbolAddress((void**)&gKl,  g_Kl);
    cudaGetSymbolAddress((void**)&gVTh, g_VTh);
    cudaGetSymbolAddress((void**)&gVTl, g_VTl);
    cudaGetSymbolAddress((void**)&gAO,  g_AO);

    const int M = B_ * S1_;
    dim3 gemm_grid(F_ / 64, M / 64);            // (4, 256)

    gemm_bias_kernel<D_, 1><<<gemm_grid, 256>>>(feat1, Wq, bq, nullptr, gQh,  gQl,  F_);
    gemm_bias_kernel<D_, 1><<<gemm_grid, 256>>>(feat2, Wk, bk, nullptr, gKh,  gKl,  F_);
    gemm_bias_kernel<D_, 2><<<gemm_grid, 256>>>(feat2, Wv, bv, nullptr, gVTh, gVTl, F_);

    cudaFuncSetAttribute(attn_kernel, cudaFuncAttributeMaxDynamicSharedMemorySize,
                         ATTN_SMEM_BYTES);
    dim3 attn_grid(S1_ / BQA, B_);              // (32, 8)
    attn_kernel<<<attn_grid, 256, ATTN_SMEM_BYTES>>>(gQh, gQl, gKh, gKl, gVTh, gVTl, gAO);

    gemm_bias_kernel<F_, 0><<<gemm_grid, 256>>>(gAO, Wfc, bfc, out, nullptr, nullptr, F_);
}

// round 5
// speedup vs baseline: 3.1185x; 1.0042x over previous
#include <cuda_runtime.h>
#include <cuda_bf16.h>
#include <cstdint>

// Problem shape
#define B_  8
#define S1_ 2048
#define S2_ 2048
#define D_  512
#define F_  256

// Scratch: split-bf16 Q/K, transposed split-bf16 V, fp32 attention output.
#define NQKV (B_ * S1_ * F_)
__device__ __align__(16) __nv_bfloat16 g_Qh [NQKV];
__device__ __align__(16) __nv_bfloat16 g_Ql [NQKV];
__device__ __align__(16) __nv_bfloat16 g_Kh [NQKV];
__device__ __align__(16) __nv_bfloat16 g_Kl [NQKV];
__device__ __align__(16) __nv_bfloat16 g_VTh[NQKV];   // [b, f, t]
__device__ __align__(16) __nv_bfloat16 g_VTl[NQKV];   // [b, f, t]
__device__ __align__(16) float         g_AO [NQKV];

// ===========================================================================
// Warp-MMA helpers (baseline PTX, valid for compute_103)
// ===========================================================================
__device__ __forceinline__ uint32_t smem_to_u32(const void* p) {
    uint32_t a;
    asm("{ .reg .u64 t; cvta.to.shared.u64 t, %1; cvt.u32.u64 %0, t; }"
        : "=r"(a) : "l"(p));
    return a;
}

__device__ __forceinline__ void ldsm4(uint32_t& r0, uint32_t& r1,
                                      uint32_t& r2, uint32_t& r3, uint32_t addr) {
    asm volatile("ldmatrix.sync.aligned.m8n8.x4.shared.b16 {%0,%1,%2,%3}, [%4];"
        : "=r"(r0), "=r"(r1), "=r"(r2), "=r"(r3) : "r"(addr));
}

__device__ __forceinline__ void mma_bf16(float (&d)[4], const uint32_t (&a)[4],
                                         uint32_t b0, uint32_t b1) {
    asm volatile(
        "mma.sync.aligned.m16n8k16.row.col.f32.bf16.bf16.f32 "
        "{%0,%1,%2,%3}, {%4,%5,%6,%7}, {%8,%9}, {%0,%1,%2,%3};"
        : "+f"(d[0]), "+f"(d[1]), "+f"(d[2]), "+f"(d[3])
        : "r"(a[0]), "r"(a[1]), "r"(a[2]), "r"(a[3]), "r"(b0), "r"(b1));
}

__device__ __forceinline__ void split_bf16(float x, __nv_bfloat16& h, __nv_bfloat16& l) {
    h = __float2bfloat16(x);
    l = __float2bfloat16(x - __bfloat162float(h));
}
__device__ __forceinline__ uint32_t pack2(__nv_bfloat16 a, __nv_bfloat16 b) {
    return (uint32_t)__bfloat16_as_ushort(a) | ((uint32_t)__bfloat16_as_ushort(b) << 16);
}

// ===========================================================================
// Tiled SIMT GEMM with bias. MODE 0: fp32 out. MODE 1: split-bf16 hi/lo out
// (row-major). MODE 2: split-bf16 hi/lo out, transposed [b, f, t].
// ===========================================================================
template<int KD, int MODE>
__global__ void __launch_bounds__(256) gemm_bias_kernel(
    const float* __restrict__ A, const float* __restrict__ W,
    const float* __restrict__ bias, float* __restrict__ Cf,
    __nv_bfloat16* __restrict__ Oh, __nv_bfloat16* __restrict__ Ol, int N)
{
    __shared__ float As[16][68];
    __shared__ float Bs[16][68];

    const int tid = threadIdx.x;
    const int tx = tid & 15;
    const int ty = tid >> 4;
    const int row0 = blockIdx.y * 64;
    const int col0 = blockIdx.x * 64;

    const int am = tid >> 2;
    const int ak = (tid & 3) * 4;
    const int wk = tid >> 4;
    const int wn = (tid & 15) * 4;

    float acc[4][4];
    #pragma unroll
    for (int i = 0; i < 4; i++)
        #pragma unroll
        for (int j = 0; j < 4; j++) acc[i][j] = 0.f;

    for (int k0 = 0; k0 < KD; k0 += 16) {
        float4 av = *(const float4*)(A + (size_t)(row0 + am) * KD + k0 + ak);
        As[ak + 0][am] = av.x;
        As[ak + 1][am] = av.y;
        As[ak + 2][am] = av.z;
        As[ak + 3][am] = av.w;
        float4 wv = *(const float4*)(W + (size_t)(k0 + wk) * N + col0 + wn);
        *(float4*)&Bs[wk][wn] = wv;
        __syncthreads();

        #pragma unroll
        for (int kk = 0; kk < 16; kk++) {
            float4 a = *(const float4*)&As[kk][ty * 4];
            float4 b = *(const float4*)&Bs[kk][tx * 4];
            acc[0][0] += a.x * b.x; acc[0][1] += a.x * b.y; acc[0][2] += a.x * b.z; acc[0][3] += a.x * b.w;
            acc[1][0] += a.y * b.x; acc[1][1] += a.y * b.y; acc[1][2] += a.y * b.z; acc[1][3] += a.y * b.w;
            acc[2][0] += a.z * b.x; acc[2][1] += a.z * b.y; acc[2][2] += a.z * b.z; acc[2][3] += a.z * b.w;
            acc[3][0] += a.w * b.x; acc[3][1] += a.w * b.y; acc[3][2] += a.w * b.z; acc[3][3] += a.w * b.w;
        }
        __syncthreads();
    }

    float4 bv = *(const float4*)(bias + col0 + tx * 4);
    float bvv[4] = {bv.x, bv.y, bv.z, bv.w};

    if (MODE == 0) {
        #pragma unroll
        for (int i = 0; i < 4; i++) {
            float4 o;
            o.x = acc[i][0] + bvv[0];
            o.y = acc[i][1] + bvv[1];
            o.z = acc[i][2] + bvv[2];
            o.w = acc[i][3] + bvv[3];
            *(float4*)(Cf + (size_t)(row0 + ty * 4 + i) * N + col0 + tx * 4) = o;
        }
    } else if (MODE == 1) {
        #pragma unroll
        for (int i = 0; i < 4; i++) {
            __nv_bfloat16 h[4], l[4];
            #pragma unroll
            for (int j = 0; j < 4; j++) split_bf16(acc[i][j] + bvv[j], h[j], l[j]);
            size_t base = (size_t)(row0 + ty * 4 + i) * N + col0 + tx * 4;
            *(uint32_t*)(Oh + base)     = pack2(h[0], h[1]);
            *(uint32_t*)(Oh + base + 2) = pack2(h[2], h[3]);
            *(uint32_t*)(Ol + base)     = pack2(l[0], l[1]);
            *(uint32_t*)(Ol + base + 2) = pack2(l[2], l[3]);
        }
    } else {
        const int b  = row0 >> 11;              // 2048 rows per batch
        const int t0 = (row0 & 2047) + ty * 4;
        #pragma unroll
        for (int j = 0; j < 4; j++) {
            const int f = col0 + tx * 4 + j;
            __nv_bfloat16 h[4], l[4];
            #pragma unroll
            for (int i = 0; i < 4; i++) split_bf16(acc[i][j] + bvv[j], h[i], l[i]);
            size_t base = ((size_t)(b * F_ + f)) * S2_ + t0;
            *(uint32_t*)(Oh + base)     = pack2(h[0], h[1]);
            *(uint32_t*)(Oh + base + 2) = pack2(h[2], h[3]);
            *(uint32_t*)(Ol + base)     = pack2(l[0], l[1]);
            *(uint32_t*)(Ol + base + 2) = pack2(l[2], l[3]);
        }
    }
}

// ===========================================================================
// HMMA flash attention (mma.sync m16n8k16 bf16, split hi/lo, no online max).
// CTA = 64 queries, 8 warps, 32 key tiles of 64.
//  S phase : warp = (qgroup 0-3) x (key-half 0-1): S[16q, 32k], 3 chains.
//  PV phase: warp = (qgroup 0-3) x (f-half 0-1):  O[16q, 128f] += P @ V.
// SMEM (bytes): QH 0, QL 32K, KH 64K, KL 96K, VH 128K, VL 160K,
//               PH 192K, PL 200K, L 208K. Total ~208.5KB, 1 CTA/SM.
// ===========================================================================
#define BQA 64
#define BKA 64
#define NKT (S2_ / BKA)

#define QH_OFF 0
#define QL_OFF 32768
#define KH_OFF 65536
#define KL_OFF 98304
#define VH_OFF 131072
#define VL_OFF 163840
#define PH_OFF 196608
#define PL_OFF 204800
#define L_OFF  212992
#define ATTN_SMEM_BYTES (212992 + 512)

__global__ void __launch_bounds__(256, 1) attn_kernel(
    const __nv_bfloat16* __restrict__ Qh, const __nv_bfloat16* __restrict__ Ql,
    const __nv_bfloat16* __restrict__ Kh, const __nv_bfloat16* __restrict__ Kl,
    const __nv_bfloat16* __restrict__ VTh, const __nv_bfloat16* __restrict__ VTl,
    float* __restrict__ AO)
{
    extern __shared__ char sm[];
    const uint32_t smb = smem_to_u32(sm);
    const int tid  = threadIdx.x;
    const int wid  = tid >> 5;
    const int lane = tid & 31;
    const int b    = blockIdx.y;
    const int q0   = blockIdx.x * BQA;
    const int qg   = wid & 3;     // query group (16 rows)
    const int kh   = wid >> 2;    // S: key half; PV: f half

    const __nv_bfloat16* Khb = Kh  + (size_t)b * S2_ * F_;
    const __nv_bfloat16* Klb = Kl  + (size_t)b * S2_ * F_;
    const __nv_bfloat16* Vhb = VTh + (size_t)b * F_ * S2_;
    const __nv_bfloat16* Vlb = VTl + (size_t)b * F_ * S2_;

    // ---- load Q tile (64 x 256 bf16, hi+lo), swizzled ----
    #pragma unroll
    for (int l = 0; l < 8; l++) {
        int id = l * 256 + tid;
        int r = id >> 5, c = id & 31;
        uint32_t off = r * 512 + ((c ^ (r & 7)) << 4);
        *(uint4*)(sm + QH_OFF + off) =
            *(const uint4*)(Qh + ((size_t)(b * S1_ + q0 + r)) * F_ + c * 8);
        *(uint4*)(sm + QL_OFF + off) =
            *(const uint4*)(Ql + ((size_t)(b * S1_ + q0 + r)) * F_ + c * 8);
    }

    // ---- per-lane fragment address bases ----
    // A-frag (Q / P): row = qg*16 + (lane&15), chunk-half = lane>>4
    const int arow = qg * 16 + (lane & 15);
    const int as   = arow & 7;
    const int ah   = lane >> 4;
    const uint32_t qbH = smb + QH_OFF + arow * 512;
    const uint32_t qbL = smb + QL_OFF + arow * 512;
    const uint32_t pbH = smb + PH_OFF + arow * 128;
    const uint32_t pbL = smb + PL_OFF + arow * 128;
    // B-frag (K / V): row = base + ((lane>>4)<<3) + (lane&7), chunk-half = (lane>>3)&1
    const int brow = ((lane >> 4) << 3) + (lane & 7);
    const int bs   = lane & 7;
    const int bh2  = (lane >> 3) & 1;
    const uint32_t kbH = smb + KH_OFF + (kh * 32 + brow) * 512;
    const uint32_t kbL = smb + KL_OFF + (kh * 32 + brow) * 512;
    const uint32_t vbH = smb + VH_OFF + (kh * 128 + brow) * 128;
    const uint32_t vbL = smb + VL_OFF + (kh * 128 + brow) * 128;
    // C-frag rows (for softmax / P store / output)
    const int crow  = qg * 16 + (lane >> 2);
    const int lq    = lane & 3;

    float accO[16][4];
    #pragma unroll
    for (int i = 0; i < 16; i++)
        #pragma unroll
        for (int j = 0; j < 4; j++) accO[i][j] = 0.f;
    float lsum0 = 0.f, lsum1 = 0.f;

    const float scale = 0.0625f;  // 1/sqrt(256)

    for (int it = 0; it < NKT; it++) {
        const int kt = it * BKA;
        __syncthreads();   // prev PV done before K/V overwrite

        // ---- load K (64x256) and VT (256x64) split tiles, swizzled ----
        #pragma unroll
        for (int l = 0; l < 8; l++) {
            int id = l * 256 + tid;
            int r = id >> 5, c = id & 31;
            uint32_t off = r * 512 + ((c ^ (r & 7)) << 4);
            *(uint4*)(sm + KH_OFF + off) =
                *(const uint4*)(Khb + (size_t)(kt + r) * F_ + c * 8);
            *(uint4*)(sm + KL_OFF + off) =
                *(const uint4*)(Klb + (size_t)(kt + r) * F_ + c * 8);
        }
        #pragma unroll
        for (int l = 0; l < 8; l++) {
            int id = l * 256 + tid;
            int r = id >> 3, c = id & 7;
            uint32_t off = r * 128 + ((c ^ (r & 7)) << 4);
            *(uint4*)(sm + VH_OFF + off) =
                *(const uint4*)(Vhb + (size_t)r * S2_ + kt + c * 8);
            *(uint4*)(sm + VL_OFF + off) =
                *(const uint4*)(Vlb + (size_t)r * S2_ + kt + c * 8);
        }
        __syncthreads();

        // ---- S = Qh@Kh + Qh@Kl + Ql@Kh  (warp: 16q x 32k) ----
        float sa[4][4];
        #pragma unroll
        for (int i = 0; i < 4; i++)
            #pragma unroll
            for (int j = 0; j < 4; j++) sa[i][j] = 0.f;

        #pragma unroll 4
        for (int ks = 0; ks < 16; ks++) {
            uint32_t aq[4], al[4], bhf[8], blf[8];
            uint32_t qc = (uint32_t)(((2 * ks + ah) ^ as) << 4);
            ldsm4(aq[0], aq[1], aq[2], aq[3], qbH + qc);
            ldsm4(al[0], al[1], al[2], al[3], qbL + qc);
            uint32_t kc = (uint32_t)(((2 * ks + bh2) ^ bs) << 4);
            ldsm4(bhf[0], bhf[1], bhf[2], bhf[3], kbH + kc);
            ldsm4(bhf[4], bhf[5], bhf[6], bhf[7], kbH + 16 * 512 + kc);
            ldsm4(blf[0], blf[1], blf[2], blf[3], kbL + kc);
            ldsm4(blf[4], blf[5], blf[6], blf[7], kbL + 16 * 512 + kc);
            #pragma unroll
            for (int nt = 0; nt < 4; nt++) {
                mma_bf16(sa[nt], aq, bhf[2 * nt], bhf[2 * nt + 1]);
                mma_bf16(sa[nt], aq, blf[2 * nt], blf[2 * nt + 1]);
                mma_bf16(sa[nt], al, bhf[2 * nt], bhf[2 * nt + 1]);
            }
        }

        // ---- softmax (no max-sub), split to bf16, store P hi/lo ----
        {
            const int rA = crow, rB = crow + 8;
            #pragma unroll
            for (int nt = 0; nt < 4; nt++) {
                float p0 = __expf(sa[nt][0] * scale);
                float p1 = __expf(sa[nt][1] * scale);
                float p2 = __expf(sa[nt][2] * scale);
                float p3 = __expf(sa[nt][3] * scale);
                lsum0 += p0 + p1;
                lsum1 += p2 + p3;
                int chunk = kh * 4 + nt;
                uint32_t offA = (uint32_t)(rA * 128 + ((chunk ^ (rA & 7)) << 4) + lq * 4);
                uint32_t offB = (uint32_t)(rB * 128 + ((chunk ^ (rB & 7)) << 4) + lq * 4);
                __nv_bfloat16 h0, l0, h1, l1, h2, l2, h3, l3;
                split_bf16(p0, h0, l0); split_bf16(p1, h1, l1);
                split_bf16(p2, h2, l2); split_bf16(p3, h3, l3);
                *(uint32_t*)(sm + PH_OFF + offA) = pack2(h0, h1);
                *(uint32_t*)(sm + PH_OFF + offB) = pack2(h2, h3);
                *(uint32_t*)(sm + PL_OFF + offA) = pack2(l0, l1);
                *(uint32_t*)(sm + PL_OFF + offB) = pack2(l2, l3);
            }
        }
        __syncthreads();

        // ---- O += Ph@Vh + Ph@Vl + Pl@Vh  (warp: 16q x 128f) ----
        {
            uint32_t pf[4][4], plf[4][4];
            #pragma unroll
            for (int ks = 0; ks < 4; ks++) {
                uint32_t pc = (uint32_t)(((2 * ks + ah) ^ as) << 4);
                ldsm4(pf[ks][0], pf[ks][1], pf[ks][2], pf[ks][3], pbH + pc);
                ldsm4(plf[ks][0], plf[ks][1], plf[ks][2], plf[ks][3], pbL + pc);
            }
            #pragma unroll 2
            for (int np = 0; np < 8; np++) {
                #pragma unroll
                for (int ks = 0; ks < 4; ks++) {
                    uint32_t vh[4], vl[4];
                    uint32_t off = (uint32_t)(np * 16 * 128 + (((2 * ks + bh2) ^ bs) << 4));
                    ldsm4(vh[0], vh[1], vh[2], vh[3], vbH + off);
                    ldsm4(vl[0], vl[1], vl[2], vl[3], vbL + off);
                    const int n0 = np * 2, n1 = np * 2 + 1;
                    mma_bf16(accO[n0], pf[ks],  vh[0], vh[1]);
                    mma_bf16(accO[n0], pf[ks],  vl[0], vl[1]);
                    mma_bf16(accO[n0], plf[ks], vh[0], vh[1]);
                    mma_bf16(accO[n1], pf[ks],  vh[2], vh[3]);
                    mma_bf16(accO[n1], pf[ks],  vl[2], vl[3]);
                    mma_bf16(accO[n1], plf[ks], vh[2], vh[3]);
                }
            }
        }
    }

    // ---- reduce l across lanes + key-halves ----
    float* lsm = (float*)(sm + L_OFF);
    lsum0 += __shfl_xor_sync(0xffffffffu, lsum0, 1);
    lsum0 += __shfl_xor_sync(0xffffffffu, lsum0, 2);
    lsum1 += __shfl_xor_sync(0xffffffffu, lsum1, 1);
    lsum1 += __shfl_xor_sync(0xffffffffu, lsum1, 2);
    __syncthreads();
    if (lq == 0) {
        lsm[kh * 64 + crow]     = lsum0;
        lsm[kh * 64 + crow + 8] = lsum1;
    }
    __syncthreads();

    // ---- normalize + store fp32 output ----
    const float inv0 = 1.f / (lsm[crow]     + lsm[64 + crow]);
    const float inv1 = 1.f / (lsm[crow + 8] + lsm[64 + crow + 8]);
    float* dst0 = AO + ((size_t)(b * S1_ + q0 + crow)) * F_;
    float* dst1 = AO + ((size_t)(b * S1_ + q0 + crow + 8)) * F_;
    #pragma unroll
    for (int nt = 0; nt < 16; nt++) {
        int col = kh * 128 + nt * 8 + 2 * lq;
        float2 o0 = make_float2(accO[nt][0] * inv0, accO[nt][1] * inv0);
        float2 o1 = make_float2(accO[nt][2] * inv1, accO[nt][3] * inv1);
        *(float2*)(dst0 + col) = o0;
        *(float2*)(dst1 + col) = o1;
    }
}

// ===========================================================================
// Launch
// ===========================================================================
extern "C" void kernel_launch(void* const* d_in, const int* in_sizes, int n_in,
                              void* d_out, int out_size)
{
    const float* feat1 = (const float*)d_in[0];
    const float* feat2 = (const float*)d_in[1];
    const float* Wq    = (const float*)d_in[2];
    const float* bq    = (const float*)d_in[3];
    const float* Wk    = (const float*)d_in[4];
    const float* bk    = (const float*)d_in[5];
    const float* Wv    = (const float*)d_in[6];
    const float* bv    = (const float*)d_in[7];
    const float* Wfc   = (const float*)d_in[8];
    const float* bfc   = (const float*)d_in[9];
    float* out = (float*)d_out;

    __nv_bfloat16 *gQh, *gQl, *gKh, *gKl, *gVTh, *gVTl;
    float* gAO;
    cudaGetSymbolAddress((void**)&gQh,  g_Qh);
    cudaGetSymbolAddress((void**)&gQl,  g_Ql);
    cudaGetSymbolAddress((void**)&gKh,  g_Kh);
    cudaGetSymbolAddress((void**)&gKl,  g_Kl);
    cudaGetSymbolAddress((void**)&gVTh, g_VTh);
    cudaGetSymbolAddress((void**)&gVTl, g_VTl);
    cudaGetSymbolAddress((void**)&gAO,  g_AO);

    const int M = B_ * S1_;
    dim3 gemm_grid(F_ / 64, M / 64);            // (4, 256)

    gemm_bias_kernel<D_, 1><<<gemm_grid, 256>>>(feat1, Wq, bq, nullptr, gQh,  gQl,  F_);
    gemm_bias_kernel<D_, 1><<<gemm_grid, 256>>>(feat2, Wk, bk, nullptr, gKh,  gKl,  F_);
    gemm_bias_kernel<D_, 2><<<gemm_grid, 256>>>(feat2, Wv, bv, nullptr, gVTh, gVTl, F_);

    cudaFuncSetAttribute(attn_kernel, cudaFuncAttributeMaxDynamicSharedMemorySize,
                         ATTN_SMEM_BYTES);
    dim3 attn_grid(S1_ / BQA, B_);              // (32, 8)
    attn_kernel<<<attn_grid, 256, ATTN_SMEM_BYTES>>>(gQh, gQl, gKh, gKl, gVTh, gVTl, gAO);

    gemm_bias_kernel<F_, 0><<<gemm_grid, 256>>>(gAO, Wfc, bfc, out, nullptr, nullptr, F_);
}

// round 6
// speedup vs baseline: 4.2291x; 1.3562x over previous
#include <cuda_runtime.h>
#include <cuda_bf16.h>
#include <cstdint>

#define B_  8
#define S1_ 2048
#define S2_ 2048
#define D_  512
#define F_  256

#define NQKV (B_ * S1_ * F_)
#define NFEAT (B_ * S1_ * D_)

__device__ __align__(16) __nv_bfloat16 g_f1h[NFEAT];
__device__ __align__(16) __nv_bfloat16 g_f1l[NFEAT];
__device__ __align__(16) __nv_bfloat16 g_f2h[NFEAT];
__device__ __align__(16) __nv_bfloat16 g_f2l[NFEAT];
__device__ __align__(16) __nv_bfloat16 g_wq[2][D_ * F_];
__device__ __align__(16) __nv_bfloat16 g_wk[2][D_ * F_];
__device__ __align__(16) __nv_bfloat16 g_wv[2][D_ * F_];
__device__ __align__(16) __nv_bfloat16 g_wf[2][F_ * F_];
__device__ __align__(16) __nv_bfloat16 g_Qh [NQKV];
__device__ __align__(16) __nv_bfloat16 g_Ql [NQKV];
__device__ __align__(16) __nv_bfloat16 g_Kh [NQKV];
__device__ __align__(16) __nv_bfloat16 g_Kl [NQKV];
__device__ __align__(16) __nv_bfloat16 g_VTh[NQKV];   // [b, f, t]
__device__ __align__(16) __nv_bfloat16 g_VTl[NQKV];
__device__ __align__(16) __nv_bfloat16 g_AOh[NQKV];
__device__ __align__(16) __nv_bfloat16 g_AOl[NQKV];

// ---------------------------------------------------------------------------
__device__ __forceinline__ uint32_t smem_to_u32(const void* p) {
    uint32_t a;
    asm("{ .reg .u64 t; cvta.to.shared.u64 t, %1; cvt.u32.u64 %0, t; }"
        : "=r"(a) : "l"(p));
    return a;
}
__device__ __forceinline__ void ldsm4(uint32_t& r0, uint32_t& r1,
                                      uint32_t& r2, uint32_t& r3, uint32_t addr) {
    asm volatile("ldmatrix.sync.aligned.m8n8.x4.shared.b16 {%0,%1,%2,%3}, [%4];"
        : "=r"(r0), "=r"(r1), "=r"(r2), "=r"(r3) : "r"(addr));
}
__device__ __forceinline__ void mma_bf16(float (&d)[4], const uint32_t (&a)[4],
                                         uint32_t b0, uint32_t b1) {
    asm volatile(
        "mma.sync.aligned.m16n8k16.row.col.f32.bf16.bf16.f32 "
        "{%0,%1,%2,%3}, {%4,%5,%6,%7}, {%8,%9}, {%0,%1,%2,%3};"
        : "+f"(d[0]), "+f"(d[1]), "+f"(d[2]), "+f"(d[3])
        : "r"(a[0]), "r"(a[1]), "r"(a[2]), "r"(a[3]), "r"(b0), "r"(b1));
}
__device__ __forceinline__ void split_bf16(float x, __nv_bfloat16& h, __nv_bfloat16& l) {
    h = __float2bfloat16(x);
    l = __float2bfloat16(x - __bfloat162float(h));
}
__device__ __forceinline__ uint32_t pack2(__nv_bfloat16 a, __nv_bfloat16 b) {
    return (uint32_t)__bfloat16_as_ushort(a) | ((uint32_t)__bfloat16_as_ushort(b) << 16);
}
#define CP_ASYNC16(dst, src) \
    asm volatile("cp.async.cg.shared.global [%0], [%1], 16;" :: "r"(dst), "l"(src))
#define CP_COMMIT() asm volatile("cp.async.commit_group;" ::: "memory")
#define CP_WAIT0()  asm volatile("cp.async.wait_group 0;" ::: "memory")

// ---------------------------------------------------------------------------
__global__ void __launch_bounds__(256) split_f32_kernel(
    const float* __restrict__ in, __nv_bfloat16* __restrict__ h,
    __nv_bfloat16* __restrict__ l, int n4)
{
    int i = blockIdx.x * 256 + threadIdx.x;
    if (i >= n4) return;
    float4 v = ((const float4*)in)[i];
    __nv_bfloat16 h0,l0,h1,l1,h2,l2,h3,l3;
    split_bf16(v.x,h0,l0); split_bf16(v.y,h1,l1);
    split_bf16(v.z,h2,l2); split_bf16(v.w,h3,l3);
    ((uint2*)h)[i] = make_uint2(pack2(h0,h1), pack2(h2,h3));
    ((uint2*)l)[i] = make_uint2(pack2(l0,l1), pack2(l2,l3));
}

// W[K][N] fp32 -> Th/Tl [N][K] split bf16
__global__ void __launch_bounds__(256) splitT_w_kernel(
    const float* __restrict__ W, __nv_bfloat16* __restrict__ Th,
    __nv_bfloat16* __restrict__ Tl, int K, int N)
{
    int i = blockIdx.x * 256 + threadIdx.x;
    if (i >= K * N) return;
    int n = i / K, k = i - n * K;
    __nv_bfloat16 h, l;
    split_bf16(W[(size_t)k * N + n], h, l);
    Th[i] = h; Tl[i] = l;
}

// ---------------------------------------------------------------------------
// HMMA GEMM: C[M,256] = A[M,KD] @ Bt[256,KD]^T + bias(N), split-bf16 3-chain.
// CTA 128x128, 8 warps (4m x 2n), k-block 64, cp.async double-buffered.
// OUT: 0 = fp32, 1 = split-bf16 row-major, 2 = split-bf16 VT [b,f,t].
// smem/buf: AH 0 AL 16K BH 32K BL 48K (64KB); two buffers = 128KB.
// ---------------------------------------------------------------------------
#define GEMM_SMEM 131072
#define GISSUE(buf, k0) do { \
    uint32_t gbase = smb + (buf) * 65536; \
    _Pragma("unroll") \
    for (int p = 0; p < 4; p++) { \
        int r = p * 32 + (tid >> 3); int c = tid & 7; \
        uint32_t d = r * 128 + (((uint32_t)(c ^ (r & 7))) << 4); \
        CP_ASYNC16(gbase + d,         Ah + (size_t)(m0 + r) * KD + (k0) + c * 8); \
        CP_ASYNC16(gbase + 16384 + d, Al + (size_t)(m0 + r) * KD + (k0) + c * 8); \
        CP_ASYNC16(gbase + 32768 + d, Bh + (size_t)(n0 + r) * KD + (k0) + c * 8); \
        CP_ASYNC16(gbase + 49152 + d, Bl + (size_t)(n0 + r) * KD + (k0) + c * 8); \
    } } while (0)

template<int KD, int OUT>
__global__ void __launch_bounds__(256, 1) gemm_hmma(
    const __nv_bfloat16* __restrict__ Ah, const __nv_bfloat16* __restrict__ Al,
    const __nv_bfloat16* __restrict__ Bh, const __nv_bfloat16* __restrict__ Bl,
    const float* __restrict__ bias, float* __restrict__ Cf,
    __nv_bfloat16* __restrict__ Oh, __nv_bfloat16* __restrict__ Ol)
{
    extern __shared__ char sm[];
    const uint32_t smb = smem_to_u32(sm);
    const int tid  = threadIdx.x;
    const int lane = tid & 31;
    const int wid  = tid >> 5;
    const int wm = wid & 3, wn = wid >> 2;
    const int n0 = blockIdx.x * 128, m0 = blockIdx.y * 128;

    const int arow = wm * 32 + (lane & 15);
    const int as   = arow & 7;
    const int ah   = lane >> 4;
    const int brow = ((lane >> 4) << 3) + (lane & 7);
    const int bs   = lane & 7;
    const int bh2  = (lane >> 3) & 1;

    float acc[2][8][4];
    #pragma unroll
    for (int i = 0; i < 2; i++)
        #pragma unroll
        for (int j = 0; j < 8; j++)
            #pragma unroll
            for (int k = 0; k < 4; k++) acc[i][j][k] = 0.f;

    const int T = KD / 64;
    GISSUE(0, 0); CP_COMMIT();

    for (int t = 0; t < T; t++) {
        CP_WAIT0();
        __syncthreads();
        if (t + 1 < T) { GISSUE((t + 1) & 1, (t + 1) * 64); CP_COMMIT(); }

        const int cur = t & 1;
        uint32_t aH = smb + cur * 65536 + arow * 128;
        uint32_t aL = aH + 16384;
        uint32_t bB = smb + cur * 65536 + 32768 + (wn * 64 + brow) * 128;

        #pragma unroll
        for (int ks = 0; ks < 4; ks++) {
            uint32_t ac = ((uint32_t)((2 * ks + ah) ^ as)) << 4;
            uint32_t aq[2][4], alr[2][4];
            ldsm4(aq[0][0], aq[0][1], aq[0][2], aq[0][3], aH + ac);
            ldsm4(aq[1][0], aq[1][1], aq[1][2], aq[1][3], aH + 16 * 128 + ac);
            ldsm4(alr[0][0], alr[0][1], alr[0][2], alr[0][3], aL + ac);
            ldsm4(alr[1][0], alr[1][1], alr[1][2], alr[1][3], aL + 16 * 128 + ac);
            uint32_t bc = ((uint32_t)((2 * ks + bh2) ^ bs)) << 4;
            #pragma unroll
            for (int ni = 0; ni < 4; ni++) {
                uint32_t bh4[4], bl4[4];
                ldsm4(bh4[0], bh4[1], bh4[2], bh4[3], bB + ni * 2048 + bc);
                ldsm4(bl4[0], bl4[1], bl4[2], bl4[3], bB + 16384 + ni * 2048 + bc);
                #pragma unroll
                for (int mi = 0; mi < 2; mi++) {
                    mma_bf16(acc[mi][2*ni],   aq[mi],  bh4[0], bh4[1]);
                    mma_bf16(acc[mi][2*ni],   aq[mi],  bl4[0], bl4[1]);
                    mma_bf16(acc[mi][2*ni],   alr[mi], bh4[0], bh4[1]);
                    mma_bf16(acc[mi][2*ni+1], aq[mi],  bh4[2], bh4[3]);
                    mma_bf16(acc[mi][2*ni+1], aq[mi],  bl4[2], bl4[3]);
                    mma_bf16(acc[mi][2*ni+1], alr[mi], bh4[2], bh4[3]);
                }
            }
        }
        __syncthreads();
    }

    const int lq = lane & 3;
    #pragma unroll
    for (int mi = 0; mi < 2; mi++) {
        int r0 = m0 + wm * 32 + mi * 16 + (lane >> 2);
        int r1 = r0 + 8;
        #pragma unroll
        for (int nt = 0; nt < 8; nt++) {
            int col = n0 + wn * 64 + nt * 8 + 2 * lq;
            float b0 = bias[col], b1 = bias[col + 1];
            float v0 = acc[mi][nt][0] + b0, v1 = acc[mi][nt][1] + b1;
            float v2 = acc[mi][nt][2] + b0, v3 = acc[mi][nt][3] + b1;
            if (OUT == 0) {
                *(float2*)(Cf + (size_t)r0 * 256 + col) = make_float2(v0, v1);
                *(float2*)(Cf + (size_t)r1 * 256 + col) = make_float2(v2, v3);
            } else {
                __nv_bfloat16 h0,l0,h1,l1,h2,l2,h3,l3;
                split_bf16(v0,h0,l0); split_bf16(v1,h1,l1);
                split_bf16(v2,h2,l2); split_bf16(v3,h3,l3);
                if (OUT == 1) {
                    size_t o0 = (size_t)r0 * 256 + col, o1 = (size_t)r1 * 256 + col;
                    *(uint32_t*)(Oh + o0) = pack2(h0, h1);
                    *(uint32_t*)(Ol + o0) = pack2(l0, l1);
                    *(uint32_t*)(Oh + o1) = pack2(h2, h3);
                    *(uint32_t*)(Ol + o1) = pack2(l2, l3);
                } else {
                    size_t o0 = (size_t)(r0 >> 11) * (F_ * S2_) + (size_t)col * S2_ + (r0 & 2047);
                    size_t o1 = (size_t)(r1 >> 11) * (F_ * S2_) + (size_t)col * S2_ + (r1 & 2047);
                    Oh[o0] = h0; Oh[o0 + S2_] = h1; Ol[o0] = l0; Ol[o0 + S2_] = l1;
                    Oh[o1] = h2; Oh[o1 + S2_] = h3; Ol[o1] = l2; Ol[o1 + S2_] = l3;
                }
            }
        }
    }
}

// ---------------------------------------------------------------------------
// HMMA flash attention, cp.async double-buffered K/V (BKA=32), no online max.
// CTA = 64q, 8 warps = (qg 0..3) x (half 0..1). S: half=key half (16k).
// PV: half=f half (128f). P via padded smem (128B rows). Split-bf16 out.
// SMEM: QH 0(32K) QL 32K | buf b @64K+64K*b: KH(16K) KL(16K) V(32K hi|lo)
//       PH 192K(8K) PL 200K(8K) LSM 208K.
// ---------------------------------------------------------------------------
#define BKA 32
#define NKT (S2_ / BKA)
#define AQH 0
#define AQL 32768
#define AKH(b) (65536 + (b) * 65536)
#define AKL(b) (81920 + (b) * 65536)
#define AV(b)  (98304 + (b) * 65536)
#define APH 196608
#define APL 204800
#define ALS 212992
#define ATTN_SMEM (212992 + 512)

#define AISSUE(buf, kt) do { \
    _Pragma("unroll") \
    for (int p = 0; p < 4; p++) { \
        int id = p * 256 + tid; int r = id >> 5, c = id & 31; \
        uint32_t d = r * 512 + (((uint32_t)(c ^ (r & 7))) << 4); \
        CP_ASYNC16(smb + AKH(buf) + d, Khb + (size_t)((kt) + r) * F_ + c * 8); \
        CP_ASYNC16(smb + AKL(buf) + d, Klb + (size_t)((kt) + r) * F_ + c * 8); \
    } \
    _Pragma("unroll") \
    for (int p = 0; p < 8; p++) { \
        int id = p * 256 + tid; int r = id >> 3, c = id & 7; \
        const __nv_bfloat16* src = (c < 4) \
            ? (Vhb + (size_t)r * S2_ + (kt) + c * 8) \
            : (Vlb + (size_t)r * S2_ + (kt) + (c - 4) * 8); \
        CP_ASYNC16(smb + AV(buf) + r * 128 + (((uint32_t)(c ^ (r & 7))) << 4), src); \
    } } while (0)

__global__ void __launch_bounds__(256, 1) attn_kernel(
    const __nv_bfloat16* __restrict__ Qh, const __nv_bfloat16* __restrict__ Ql,
    const __nv_bfloat16* __restrict__ Kh, const __nv_bfloat16* __restrict__ Kl,
    const __nv_bfloat16* __restrict__ VTh, const __nv_bfloat16* __restrict__ VTl,
    __nv_bfloat16* __restrict__ AOh, __nv_bfloat16* __restrict__ AOl)
{
    extern __shared__ char sm[];
    const uint32_t smb = smem_to_u32(sm);
    const int tid  = threadIdx.x;
    const int wid  = tid >> 5;
    const int lane = tid & 31;
    const int b    = blockIdx.y;
    const int q0   = blockIdx.x * 64;
    const int qg   = wid & 3;
    const int kh   = wid >> 2;

    const __nv_bfloat16* Khb = Kh  + (size_t)b * S2_ * F_;
    const __nv_bfloat16* Klb = Kl  + (size_t)b * S2_ * F_;
    const __nv_bfloat16* Vhb = VTh + (size_t)b * F_ * S2_;
    const __nv_bfloat16* Vlb = VTl + (size_t)b * F_ * S2_;

    AISSUE(0, 0); CP_COMMIT();

    // Q tile load (plain LDG, once)
    #pragma unroll
    for (int l = 0; l < 8; l++) {
        int id = l * 256 + tid;
        int r = id >> 5, c = id & 31;
        uint32_t off = r * 512 + (((uint32_t)(c ^ (r & 7))) << 4);
        *(uint4*)(sm + AQH + off) =
            *(const uint4*)(Qh + ((size_t)(b * S1_ + q0 + r)) * F_ + c * 8);
        *(uint4*)(sm + AQL + off) =
            *(const uint4*)(Ql + ((size_t)(b * S1_ + q0 + r)) * F_ + c * 8);
    }

    const int arow = qg * 16 + (lane & 15);
    const int as   = arow & 7;
    const int ah   = lane >> 4;
    const uint32_t qbH = smb + AQH + arow * 512;
    const uint32_t qbL = smb + AQL + arow * 512;
    const uint32_t pbH = smb + APH + arow * 128;
    const uint32_t pbL = smb + APL + arow * 128;
    const int brow = ((lane >> 4) << 3) + (lane & 7);
    const int bs   = lane & 7;
    const int bh2  = (lane >> 3) & 1;
    const int crow = qg * 16 + (lane >> 2);
    const int lq   = lane & 3;

    float accO[16][4];
    #pragma unroll
    for (int i = 0; i < 16; i++)
        #pragma unroll
        for (int j = 0; j < 4; j++) accO[i][j] = 0.f;
    float lsum0 = 0.f, lsum1 = 0.f;
    const float scale = 0.0625f;

    for (int it = 0; it < NKT; it++) {
        const int cur = it & 1;
        CP_WAIT0();
        __syncthreads();
        if (it + 1 < NKT) { AISSUE(cur ^ 1, (it + 1) * BKA); CP_COMMIT(); }

        // ---- S = Qh@Kh + Qh@Kl + Ql@Kh : warp 16q x 16k ----
        float sa[2][4];
        #pragma unroll
        for (int j = 0; j < 4; j++) { sa[0][j] = 0.f; sa[1][j] = 0.f; }
        const uint32_t kbH = smb + AKH(cur) + (kh * 16 + brow) * 512;
        const uint32_t kbL = smb + AKL(cur) + (kh * 16 + brow) * 512;
        #pragma unroll 4
        for (int ks = 0; ks < 16; ks++) {
            uint32_t aq[4], al4[4], bh4[4], bl4[4];
            uint32_t qc = ((uint32_t)((2 * ks + ah) ^ as)) << 4;
            ldsm4(aq[0], aq[1], aq[2], aq[3], qbH + qc);
            ldsm4(al4[0], al4[1], al4[2], al4[3], qbL + qc);
            uint32_t kc = ((uint32_t)((2 * ks + bh2) ^ bs)) << 4;
            ldsm4(bh4[0], bh4[1], bh4[2], bh4[3], kbH + kc);
            ldsm4(bl4[0], bl4[1], bl4[2], bl4[3], kbL + kc);
            mma_bf16(sa[0], aq,  bh4[0], bh4[1]);
            mma_bf16(sa[0], aq,  bl4[0], bl4[1]);
            mma_bf16(sa[0], al4, bh4[0], bh4[1]);
            mma_bf16(sa[1], aq,  bh4[2], bh4[3]);
            mma_bf16(sa[1], aq,  bl4[2], bl4[3]);
            mma_bf16(sa[1], al4, bh4[2], bh4[3]);
        }

        // ---- softmax (no max-sub), split, store P (padded 128B rows) ----
        {
            const int rA = crow, rB = crow + 8;
            #pragma unroll
            for (int nt = 0; nt < 2; nt++) {
                float p0 = __expf(sa[nt][0] * scale);
                float p1 = __expf(sa[nt][1] * scale);
                float p2 = __expf(sa[nt][2] * scale);
                float p3 = __expf(sa[nt][3] * scale);
                lsum0 += p0 + p1;
                lsum1 += p2 + p3;
                int chunk = kh * 2 + nt;
                uint32_t offA = (uint32_t)(rA * 128 + ((chunk ^ (rA & 7)) << 4) + lq * 4);
                uint32_t offB = (uint32_t)(rB * 128 + ((chunk ^ (rB & 7)) << 4) + lq * 4);
                __nv_bfloat16 h0,l0,h1,l1,h2,l2,h3,l3;
                split_bf16(p0,h0,l0); split_bf16(p1,h1,l1);
                split_bf16(p2,h2,l2); split_bf16(p3,h3,l3);
                *(uint32_t*)(sm + APH + offA) = pack2(h0, h1);
                *(uint32_t*)(sm + APH + offB) = pack2(h2, h3);
                *(uint32_t*)(sm + APL + offA) = pack2(l0, l1);
                *(uint32_t*)(sm + APL + offB) = pack2(l2, l3);
            }
        }
        __syncthreads();

        // ---- O += Ph@Vh + Ph@Vl + Pl@Vh : warp 16q x 128f ----
        {
            uint32_t pf[2][4], plf[2][4];
            #pragma unroll
            for (int ks = 0; ks < 2; ks++) {
                uint32_t pc = ((uint32_t)((2 * ks + ah) ^ as)) << 4;
                ldsm4(pf[ks][0], pf[ks][1], pf[ks][2], pf[ks][3], pbH + pc);
                ldsm4(plf[ks][0], plf[ks][1], plf[ks][2], plf[ks][3], pbL + pc);
            }
            const uint32_t vb = smb + AV(cur) + (kh * 128 + brow) * 128;
            #pragma unroll 4
            for (int np = 0; np < 8; np++) {
                #pragma unroll
                for (int ks = 0; ks < 2; ks++) {
                    uint32_t vh4[4], vl4[4];
                    uint32_t ch = (uint32_t)(2 * ks + bh2);
                    uint32_t base = vb + np * 16 * 128;
                    ldsm4(vh4[0], vh4[1], vh4[2], vh4[3],
                          base + ((ch ^ (uint32_t)bs) << 4));
                    ldsm4(vl4[0], vl4[1], vl4[2], vl4[3],
                          base + (((ch + 4) ^ (uint32_t)bs) << 4));
                    const int n0 = np * 2, n1 = np * 2 + 1;
                    mma_bf16(accO[n0], pf[ks],  vh4[0], vh4[1]);
                    mma_bf16(accO[n0], pf[ks],  vl4[0], vl4[1]);
                    mma_bf16(accO[n0], plf[ks], vh4[0], vh4[1]);
                    mma_bf16(accO[n1], pf[ks],  vh4[2], vh4[3]);
                    mma_bf16(accO[n1], pf[ks],  vl4[2], vl4[3]);
                    mma_bf16(accO[n1], plf[ks], vh4[2], vh4[3]);
                }
            }
        }
    }

    // ---- reduce l, normalize, split-bf16 output ----
    float* lsm = (float*)(sm + ALS);
    lsum0 += __shfl_xor_sync(0xffffffffu, lsum0, 1);
    lsum0 += __shfl_xor_sync(0xffffffffu, lsum0, 2);
    lsum1 += __shfl_xor_sync(0xffffffffu, lsum1, 1);
    lsum1 += __shfl_xor_sync(0xffffffffu, lsum1, 2);
    __syncthreads();
    if (lq == 0) {
        lsm[kh * 64 + crow]     = lsum0;
        lsm[kh * 64 + crow + 8] = lsum1;
    }
    __syncthreads();

    const float inv0 = 1.f / (lsm[crow]     + lsm[64 + crow]);
    const float inv1 = 1.f / (lsm[crow + 8] + lsm[64 + crow + 8]);
    const size_t base0 = ((size_t)(b * S1_ + q0 + crow)) * F_;
    const size_t base1 = ((size_t)(b * S1_ + q0 + crow + 8)) * F_;
    #pragma unroll
    for (int nt = 0; nt < 16; nt++) {
        int col = kh * 128 + nt * 8 + 2 * lq;
        __nv_bfloat16 h0,l0,h1,l1,h2,l2,h3,l3;
        split_bf16(accO[nt][0] * inv0, h0, l0);
        split_bf16(accO[nt][1] * inv0, h1, l1);
        split_bf16(accO[nt][2] * inv1, h2, l2);
        split_bf16(accO[nt][3] * inv1, h3, l3);
        *(uint32_t*)(AOh + base0 + col) = pack2(h0, h1);
        *(uint32_t*)(AOl + base0 + col) = pack2(l0, l1);
        *(uint32_t*)(AOh + base1 + col) = pack2(h2, h3);
        *(uint32_t*)(AOl + base1 + col) = pack2(l2, l3);
    }
}

// ---------------------------------------------------------------------------
extern "C" void kernel_launch(void* const* d_in, const int* in_sizes, int n_in,
                              void* d_out, int out_size)
{
    const float* feat1 = (const float*)d_in[0];
    const float* feat2 = (const float*)d_in[1];
    const float* Wq    = (const float*)d_in[2];
    const float* bq    = (const float*)d_in[3];
    const float* Wk    = (const float*)d_in[4];
    const float* bk    = (const float*)d_in[5];
    const float* Wv    = (const float*)d_in[6];
    const float* bv    = (const float*)d_in[7];
    const float* Wfc   = (const float*)d_in[8];
    const float* bfc   = (const float*)d_in[9];
    float* out = (float*)d_out;

    __nv_bfloat16 *f1h, *f1l, *f2h, *f2l, *Qh, *Ql, *Kh, *Kl, *VTh, *VTl, *AOh, *AOl;
    __nv_bfloat16 (*wq)[D_ * F_]; __nv_bfloat16 (*wk)[D_ * F_];
    __nv_bfloat16 (*wv)[D_ * F_]; __nv_bfloat16 (*wf)[F_ * F_];
    cudaGetSymbolAddress((void**)&f1h, g_f1h);
    cudaGetSymbolAddress((void**)&f1l, g_f1l);
    cudaGetSymbolAddress((void**)&f2h, g_f2h);
    cudaGetSymbolAddress((void**)&f2l, g_f2l);
    cudaGetSymbolAddress((void**)&wq,  g_wq);
    cudaGetSymbolAddress((void**)&wk,  g_wk);
    cudaGetSymbolAddress((void**)&wv,  g_wv);
    cudaGetSymbolAddress((void**)&wf,  g_wf);
    cudaGetSymbolAddress((void**)&Qh,  g_Qh);
    cudaGetSymbolAddress((void**)&Ql,  g_Ql);
    cudaGetSymbolAddress((void**)&Kh,  g_Kh);
    cudaGetSymbolAddress((void**)&Kl,  g_Kl);
    cudaGetSymbolAddress((void**)&VTh, g_VTh);
    cudaGetSymbolAddress((void**)&VTl, g_VTl);
    cudaGetSymbolAddress((void**)&AOh, g_AOh);
    cudaGetSymbolAddress((void**)&AOl, g_AOl);

    // input splits
    split_f32_kernel<<<NFEAT / 4 / 256, 256>>>(feat1, f1h, f1l, NFEAT / 4);
    split_f32_kernel<<<NFEAT / 4 / 256, 256>>>(feat2, f2h, f2l, NFEAT / 4);
    splitT_w_kernel<<<D_ * F_ / 256, 256>>>(Wq, wq[0], wq[1], D_, F_);
    splitT_w_kernel<<<D_ * F_ / 256, 256>>>(Wk, wk[0], wk[1], D_, F_);
    splitT_w_kernel<<<D_ * F_ / 256, 256>>>(Wv, wv[0], wv[1], D_, F_);
    splitT_w_kernel<<<F_ * F_ / 256, 256>>>(Wfc, wf[0], wf[1], F_, F_);

    dim3 gg(2, B_ * S1_ / 128);     // (2, 128)
    cudaFuncSetAttribute(gemm_hmma<D_, 1>, cudaFuncAttributeMaxDynamicSharedMemorySize, GEMM_SMEM);
    cudaFuncSetAttribute(gemm_hmma<D_, 2>, cudaFuncAttributeMaxDynamicSharedMemorySize, GEMM_SMEM);
    cudaFuncSetAttribute(gemm_hmma<F_, 0>, cudaFuncAttributeMaxDynamicSharedMemorySize, GEMM_SMEM);

    gemm_hmma<D_, 1><<<gg, 256, GEMM_SMEM>>>(f1h, f1l, wq[0], wq[1], bq, nullptr, Qh, Ql);
    gemm_hmma<D_, 1><<<gg, 256, GEMM_SMEM>>>(f2h, f2l, wk[0], wk[1], bk, nullptr, Kh, Kl);
    gemm_hmma<D_, 2><<<gg, 256, GEMM_SMEM>>>(f2h, f2l, wv[0], wv[1], bv, nullptr, VTh, VTl);

    cudaFuncSetAttribute(attn_kernel, cudaFuncAttributeMaxDynamicSharedMemorySize, ATTN_SMEM);
    dim3 ag(S1_ / 64, B_);          // (32, 8)
    attn_kernel<<<ag, 256, ATTN_SMEM>>>(Qh, Ql, Kh, Kl, VTh, VTl, AOh, AOl);

    gemm_hmma<F_, 0><<<gg, 256, GEMM_SMEM>>>(AOh, AOl, wf[0], wf[1], bfc, out, nullptr, nullptr);
}

// round 8
// speedup vs baseline: 4.6271x; 1.0941x over previous
#include <cuda_runtime.h>
#include <cuda_bf16.h>
#include <cstdint>

#define B_  8
#define S1_ 2048
#define S2_ 2048
#define D_  512
#define F_  256

#define NQKV (B_ * S1_ * F_)
#define NFEAT (B_ * S1_ * D_)

__device__ __align__(16) __nv_bfloat16 g_f1h[NFEAT];
__device__ __align__(16) __nv_bfloat16 g_f1l[NFEAT];
__device__ __align__(16) __nv_bfloat16 g_f2h[NFEAT];
__device__ __align__(16) __nv_bfloat16 g_f2l[NFEAT];
__device__ __align__(16) __nv_bfloat16 g_wq[2][D_ * F_];
__device__ __align__(16) __nv_bfloat16 g_wk[2][D_ * F_];
__device__ __align__(16) __nv_bfloat16 g_wv[2][D_ * F_];
__device__ __align__(16) __nv_bfloat16 g_wf[2][F_ * F_];
__device__ __align__(16) __nv_bfloat16 g_Qh [NQKV];
__device__ __align__(16) __nv_bfloat16 g_Ql [NQKV];
__device__ __align__(16) __nv_bfloat16 g_Kh [NQKV];
__device__ __align__(16) __nv_bfloat16 g_Kl [NQKV];
__device__ __align__(16) __nv_bfloat16 g_VTh[NQKV];   // [b, f, t]
__device__ __align__(16) __nv_bfloat16 g_VTl[NQKV];
__device__ __align__(16) __nv_bfloat16 g_AOh[NQKV];
__device__ __align__(16) __nv_bfloat16 g_AOl[NQKV];

// ---------------------------------------------------------------------------
__device__ __forceinline__ uint32_t smem_to_u32(const void* p) {
    uint32_t a;
    asm("{ .reg .u64 t; cvta.to.shared.u64 t, %1; cvt.u32.u64 %0, t; }"
        : "=r"(a) : "l"(p));
    return a;
}
__device__ __forceinline__ void ldsm4(uint32_t& r0, uint32_t& r1,
                                      uint32_t& r2, uint32_t& r3, uint32_t addr) {
    asm volatile("ldmatrix.sync.aligned.m8n8.x4.shared.b16 {%0,%1,%2,%3}, [%4];"
        : "=r"(r0), "=r"(r1), "=r"(r2), "=r"(r3) : "r"(addr));
}
__device__ __forceinline__ void mma_bf16(float (&d)[4], const uint32_t (&a)[4],
                                         uint32_t b0, uint32_t b1) {
    asm volatile(
        "mma.sync.aligned.m16n8k16.row.col.f32.bf16.bf16.f32 "
        "{%0,%1,%2,%3}, {%4,%5,%6,%7}, {%8,%9}, {%0,%1,%2,%3};"
        : "+f"(d[0]), "+f"(d[1]), "+f"(d[2]), "+f"(d[3])
        : "r"(a[0]), "r"(a[1]), "r"(a[2]), "r"(a[3]), "r"(b0), "r"(b1));
}
__device__ __forceinline__ void split_bf16(float x, __nv_bfloat16& h, __nv_bfloat16& l) {
    h = __float2bfloat16(x);
    l = __float2bfloat16(x - __bfloat162float(h));
}
__device__ __forceinline__ uint32_t pack2(__nv_bfloat16 a, __nv_bfloat16 b) {
    return (uint32_t)__bfloat16_as_ushort(a) | ((uint32_t)__bfloat16_as_ushort(b) << 16);
}
#define CP_ASYNC16(dst, src) \
    asm volatile("cp.async.cg.shared.global [%0], [%1], 16;" :: "r"(dst), "l"(src))
#define CP_COMMIT() asm volatile("cp.async.commit_group;" ::: "memory")
#define CP_WAIT0()  asm volatile("cp.async.wait_group 0;" ::: "memory")

// ---------------------------------------------------------------------------
__global__ void __launch_bounds__(256) split_f32_kernel(
    const float* __restrict__ in, __nv_bfloat16* __restrict__ h,
    __nv_bfloat16* __restrict__ l, int n4)
{
    int i = blockIdx.x * 256 + threadIdx.x;
    if (i >= n4) return;
    float4 v = ((const float4*)in)[i];
    __nv_bfloat16 h0,l0,h1,l1,h2,l2,h3,l3;
    split_bf16(v.x,h0,l0); split_bf16(v.y,h1,l1);
    split_bf16(v.z,h2,l2); split_bf16(v.w,h3,l3);
    ((uint2*)h)[i] = make_uint2(pack2(h0,h1), pack2(h2,h3));
    ((uint2*)l)[i] = make_uint2(pack2(l0,l1), pack2(l2,l3));
}

// All weights split + transpose in one launch.
__global__ void __launch_bounds__(256) split_weights_kernel(
    const float* __restrict__ Wq, const float* __restrict__ Wk,
    const float* __restrict__ Wv, const float* __restrict__ Wfc,
    __nv_bfloat16* __restrict__ wq0, __nv_bfloat16* __restrict__ wq1,
    __nv_bfloat16* __restrict__ wk0, __nv_bfloat16* __restrict__ wk1,
    __nv_bfloat16* __restrict__ wv0, __nv_bfloat16* __restrict__ wv1,
    __nv_bfloat16* __restrict__ wf0, __nv_bfloat16* __restrict__ wf1)
{
    int i = blockIdx.x * 256 + threadIdx.x;
    const int NW = D_ * F_;
    __nv_bfloat16 h, l;
    if (i < 3 * NW) {
        int which = i / NW, j = i - which * NW;
        int n = j / D_, k = j - n * D_;
        const float* W = which == 0 ? Wq : (which == 1 ? Wk : Wv);
        split_bf16(W[(size_t)k * F_ + n], h, l);
        __nv_bfloat16* Th = which == 0 ? wq0 : (which == 1 ? wk0 : wv0);
        __nv_bfloat16* Tl = which == 0 ? wq1 : (which == 1 ? wk1 : wv1);
        Th[j] = h; Tl[j] = l;
    } else {
        int j = i - 3 * NW;
        if (j >= F_ * F_) return;
        int n = j / F_, k = j - n * F_;
        split_bf16(Wfc[(size_t)k * F_ + n], h, l);
        wf0[j] = h; wf1[j] = l;
    }
}

// ---------------------------------------------------------------------------
// HMMA GEMM core (CTA 128x128, 8 warps 4mx2n, k-block 64, double-buffered).
// KDV threaded through both macros explicitly.
// ---------------------------------------------------------------------------
#define GEMM_SMEM 131072
#define GISSUE(buf, k0, KDV) do { \
    uint32_t gbase = smb + (buf) * 65536; \
    _Pragma("unroll") \
    for (int p = 0; p < 4; p++) { \
        int r = p * 32 + (tid >> 3); int c = tid & 7; \
        uint32_t d = r * 128 + (((uint32_t)(c ^ (r & 7))) << 4); \
        CP_ASYNC16(gbase + d,         Ah + (size_t)(m0 + r) * (KDV) + (k0) + c * 8); \
        CP_ASYNC16(gbase + 16384 + d, Al + (size_t)(m0 + r) * (KDV) + (k0) + c * 8); \
        CP_ASYNC16(gbase + 32768 + d, Bh + (size_t)(n0 + r) * (KDV) + (k0) + c * 8); \
        CP_ASYNC16(gbase + 49152 + d, Bl + (size_t)(n0 + r) * (KDV) + (k0) + c * 8); \
    } } while (0)

#define GEMM_BODY(KDV) \
    float acc[2][8][4]; \
    _Pragma("unroll") \
    for (int i = 0; i < 2; i++) \
        _Pragma("unroll") \
        for (int j = 0; j < 8; j++) \
            _Pragma("unroll") \
            for (int k = 0; k < 4; k++) acc[i][j][k] = 0.f; \
    const int T = (KDV) / 64; \
    GISSUE(0, 0, KDV); CP_COMMIT(); \
    for (int t = 0; t < T; t++) { \
        CP_WAIT0(); \
        __syncthreads(); \
        if (t + 1 < T) { GISSUE((t + 1) & 1, (t + 1) * 64, KDV); CP_COMMIT(); } \
        const int cur = t & 1; \
        uint32_t aH = smb + cur * 65536 + arow * 128; \
        uint32_t aL = aH + 16384; \
        uint32_t bB = smb + cur * 65536 + 32768 + (wn * 64 + brow) * 128; \
        _Pragma("unroll") \
        for (int ks = 0; ks < 4; ks++) { \
            uint32_t ac = ((uint32_t)((2 * ks + ah) ^ as)) << 4; \
            uint32_t aq[2][4], alr[2][4]; \
            ldsm4(aq[0][0], aq[0][1], aq[0][2], aq[0][3], aH + ac); \
            ldsm4(aq[1][0], aq[1][1], aq[1][2], aq[1][3], aH + 16 * 128 + ac); \
            ldsm4(alr[0][0], alr[0][1], alr[0][2], alr[0][3], aL + ac); \
            ldsm4(alr[1][0], alr[1][1], alr[1][2], alr[1][3], aL + 16 * 128 + ac); \
            uint32_t bc = ((uint32_t)((2 * ks + bh2) ^ bs)) << 4; \
            _Pragma("unroll") \
            for (int ni = 0; ni < 4; ni++) { \
                uint32_t bh4[4], bl4[4]; \
                ldsm4(bh4[0], bh4[1], bh4[2], bh4[3], bB + ni * 2048 + bc); \
                ldsm4(bl4[0], bl4[1], bl4[2], bl4[3], bB + 16384 + ni * 2048 + bc); \
                _Pragma("unroll") \
                for (int mi = 0; mi < 2; mi++) { \
                    mma_bf16(acc[mi][2*ni],   aq[mi],  bh4[0], bh4[1]); \
                    mma_bf16(acc[mi][2*ni],   aq[mi],  bl4[0], bl4[1]); \
                    mma_bf16(acc[mi][2*ni],   alr[mi], bh4[0], bh4[1]); \
                    mma_bf16(acc[mi][2*ni+1], aq[mi],  bh4[2], bh4[3]); \
                    mma_bf16(acc[mi][2*ni+1], aq[mi],  bl4[2], bl4[3]); \
                    mma_bf16(acc[mi][2*ni+1], alr[mi], bh4[2], bh4[3]); \
                } \
            } \
        } \
        __syncthreads(); \
    }

// Fused Q/K/V projection GEMM: blockIdx.z selects product.
__global__ void __launch_bounds__(256, 1) gemm_qkv(
    const __nv_bfloat16* __restrict__ f1h, const __nv_bfloat16* __restrict__ f1l,
    const __nv_bfloat16* __restrict__ f2h, const __nv_bfloat16* __restrict__ f2l,
    const __nv_bfloat16* __restrict__ wqh, const __nv_bfloat16* __restrict__ wql,
    const __nv_bfloat16* __restrict__ wkh, const __nv_bfloat16* __restrict__ wkl,
    const __nv_bfloat16* __restrict__ wvh, const __nv_bfloat16* __restrict__ wvl,
    const float* __restrict__ bq, const float* __restrict__ bk,
    const float* __restrict__ bv,
    __nv_bfloat16* __restrict__ Qh, __nv_bfloat16* __restrict__ Ql,
    __nv_bfloat16* __restrict__ Kh, __nv_bfloat16* __restrict__ Kl,
    __nv_bfloat16* __restrict__ VTh, __nv_bfloat16* __restrict__ VTl)
{
    extern __shared__ char sm[];
    const uint32_t smb = smem_to_u32(sm);
    const int tid  = threadIdx.x;
    const int lane = tid & 31;
    const int wid  = tid >> 5;
    const int wm = wid & 3, wn = wid >> 2;
    const int n0 = blockIdx.x * 128, m0 = blockIdx.y * 128;
    const int z  = blockIdx.z;

    const __nv_bfloat16* Ah = z == 0 ? f1h : f2h;
    const __nv_bfloat16* Al = z == 0 ? f1l : f2l;
    const __nv_bfloat16* Bh = z == 0 ? wqh : (z == 1 ? wkh : wvh);
    const __nv_bfloat16* Bl = z == 0 ? wql : (z == 1 ? wkl : wvl);
    const float* bias = z == 0 ? bq : (z == 1 ? bk : bv);
    __nv_bfloat16* Oh = z == 0 ? Qh : (z == 1 ? Kh : VTh);
    __nv_bfloat16* Ol = z == 0 ? Ql : (z == 1 ? Kl : VTl);

    const int arow = wm * 32 + (lane & 15);
    const int as   = arow & 7;
    const int ah   = lane >> 4;
    const int brow = ((lane >> 4) << 3) + (lane & 7);
    const int bs   = lane & 7;
    const int bh2  = (lane >> 3) & 1;

    GEMM_BODY(D_)

    const int lq = lane & 3;
    #pragma unroll
    for (int mi = 0; mi < 2; mi++) {
        int r0 = m0 + wm * 32 + mi * 16 + (lane >> 2);
        int r1 = r0 + 8;
        #pragma unroll
        for (int nt = 0; nt < 8; nt++) {
            int col = n0 + wn * 64 + nt * 8 + 2 * lq;
            float b0 = bias[col], b1 = bias[col + 1];
            float v0 = acc[mi][nt][0] + b0, v1 = acc[mi][nt][1] + b1;
            float v2 = acc[mi][nt][2] + b0, v3 = acc[mi][nt][3] + b1;
            __nv_bfloat16 h0,l0,h1,l1,h2,l2,h3,l3;
            split_bf16(v0,h0,l0); split_bf16(v1,h1,l1);
            split_bf16(v2,h2,l2); split_bf16(v3,h3,l3);
            if (z < 2) {
                size_t o0 = (size_t)r0 * 256 + col, o1 = (size_t)r1 * 256 + col;
                *(uint32_t*)(Oh + o0) = pack2(h0, h1);
                *(uint32_t*)(Ol + o0) = pack2(l0, l1);
                *(uint32_t*)(Oh + o1) = pack2(h2, h3);
                *(uint32_t*)(Ol + o1) = pack2(l2, l3);
            } else {
                size_t o0 = (size_t)(r0 >> 11) * (F_ * S2_) + (size_t)col * S2_ + (r0 & 2047);
                size_t o1 = (size_t)(r1 >> 11) * (F_ * S2_) + (size_t)col * S2_ + (r1 & 2047);
                Oh[o0] = h0; Oh[o0 + S2_] = h1; Ol[o0] = l0; Ol[o0 + S2_] = l1;
                Oh[o1] = h2; Oh[o1 + S2_] = h3; Ol[o1] = l2; Ol[o1 + S2_] = l3;
            }
        }
    }
}

// FC GEMM (fp32 output to d_out)
__global__ void __launch_bounds__(256, 1) gemm_fc(
    const __nv_bfloat16* __restrict__ Ah, const __nv_bfloat16* __restrict__ Al,
    const __nv_bfloat16* __restrict__ Bh, const __nv_bfloat16* __restrict__ Bl,
    const float* __restrict__ bias, float* __restrict__ Cf)
{
    extern __shared__ char sm[];
    const uint32_t smb = smem_to_u32(sm);
    const int tid  = threadIdx.x;
    const int lane = tid & 31;
    const int wid  = tid >> 5;
    const int wm = wid & 3, wn = wid >> 2;
    const int n0 = blockIdx.x * 128, m0 = blockIdx.y * 128;

    const int arow = wm * 32 + (lane & 15);
    const int as   = arow & 7;
    const int ah   = lane >> 4;
    const int brow = ((lane >> 4) << 3) + (lane & 7);
    const int bs   = lane & 7;
    const int bh2  = (lane >> 3) & 1;

    GEMM_BODY(F_)

    const int lq = lane & 3;
    #pragma unroll
    for (int mi = 0; mi < 2; mi++) {
        int r0 = m0 + wm * 32 + mi * 16 + (lane >> 2);
        int r1 = r0 + 8;
        #pragma unroll
        for (int nt = 0; nt < 8; nt++) {
            int col = n0 + wn * 64 + nt * 8 + 2 * lq;
            float b0 = bias[col], b1 = bias[col + 1];
            *(float2*)(Cf + (size_t)r0 * 256 + col) =
                make_float2(acc[mi][nt][0] + b0, acc[mi][nt][1] + b1);
            *(float2*)(Cf + (size_t)r1 * 256 + col) =
                make_float2(acc[mi][nt][2] + b0, acc[mi][nt][3] + b1);
        }
    }
}

// ---------------------------------------------------------------------------
// HMMA flash attention v3: 512 threads (16 warps = 8 qg x 2 kh), BQA=128,
// BKA=32 double-buffered cp.async, Qh fragments in registers (gmem direct),
// Ql in smem, Ph|Pl packed in one 128B row. No online max. Split-bf16 out.
// SMEM: QL 0(64K) | buf b @64K+64K*b: KH(16K) KL(16K) V(32K hi|lo)
//       P 192K(16K: hi ch0-3, lo ch4-7) LSM 208K(1K).
// ---------------------------------------------------------------------------
#define BQA 128
#define BKA 32
#define NKT (S2_ / BKA)
#define AQL 0
#define AKH(b) (65536 + (b) * 65536)
#define AKL(b) (81920 + (b) * 65536)
#define AV(b)  (98304 + (b) * 65536)
#define APS 196608
#define ALS 212992
#define ATTN_SMEM (212992 + 1024)

#define AISSUE(buf, kt) do { \
    _Pragma("unroll") \
    for (int p = 0; p < 2; p++) { \
        int id = p * 512 + tid; int r = id >> 5, c = id & 31; \
        uint32_t d = r * 512 + (((uint32_t)(c ^ (r & 7))) << 4); \
        CP_ASYNC16(smb + AKH(buf) + d, Khb + (size_t)((kt) + r) * F_ + c * 8); \
        CP_ASYNC16(smb + AKL(buf) + d, Klb + (size_t)((kt) + r) * F_ + c * 8); \
    } \
    _Pragma("unroll") \
    for (int p = 0; p < 4; p++) { \
        int id = p * 512 + tid; int r = id >> 3, c = id & 7; \
        const __nv_bfloat16* src = (c < 4) \
            ? (Vhb + (size_t)r * S2_ + (kt) + c * 8) \
            : (Vlb + (size_t)r * S2_ + (kt) + (c - 4) * 8); \
        CP_ASYNC16(smb + AV(buf) + r * 128 + (((uint32_t)(c ^ (r & 7))) << 4), src); \
    } } while (0)

__global__ void __launch_bounds__(512, 1) attn_kernel(
    const __nv_bfloat16* __restrict__ Qh, const __nv_bfloat16* __restrict__ Ql,
    const __nv_bfloat16* __restrict__ Kh, const __nv_bfloat16* __restrict__ Kl,
    const __nv_bfloat16* __restrict__ VTh, const __nv_bfloat16* __restrict__ VTl,
    __nv_bfloat16* __restrict__ AOh, __nv_bfloat16* __restrict__ AOl)
{
    extern __shared__ char sm[];
    const uint32_t smb = smem_to_u32(sm);
    const int tid  = threadIdx.x;
    const int wid  = tid >> 5;
    const int lane = tid & 31;
    const int b    = blockIdx.y;
    const int q0   = blockIdx.x * BQA;
    const int qg   = wid >> 1;      // 0..7 : 16 query rows each
    const int kh   = wid & 1;       // S: key half; PV: f half

    const __nv_bfloat16* Khb = Kh  + (size_t)b * S2_ * F_;
    const __nv_bfloat16* Klb = Kl  + (size_t)b * S2_ * F_;
    const __nv_bfloat16* Vhb = VTh + (size_t)b * F_ * S2_;
    const __nv_bfloat16* Vlb = VTl + (size_t)b * F_ * S2_;
    const __nv_bfloat16* Qlb = Ql  + ((size_t)(b * S1_ + q0)) * F_;
    const __nv_bfloat16* Qhb = Qh  + ((size_t)(b * S1_ + q0)) * F_;

    // issue Ql tile + first K/V buffer
    AISSUE(0, 0);
    #pragma unroll
    for (int p = 0; p < 8; p++) {
        int id = p * 512 + tid;
        int r = id >> 5, c = id & 31;
        uint32_t d = r * 512 + (((uint32_t)(c ^ (r & 7))) << 4);
        CP_ASYNC16(smb + AQL + d, Qlb + (size_t)r * F_ + c * 8);
    }
    CP_COMMIT();

    // Qh A-fragments loaded directly from gmem into registers (once)
    const int fr0 = qg * 16 + (lane >> 2);
    const int fcc = (lane & 3) * 2;
    uint32_t qf[16][4];
    #pragma unroll
    for (int ks = 0; ks < 16; ks++) {
        qf[ks][0] = *(const uint32_t*)(Qhb + (size_t)fr0 * F_ + 16 * ks + fcc);
        qf[ks][1] = *(const uint32_t*)(Qhb + (size_t)(fr0 + 8) * F_ + 16 * ks + fcc);
        qf[ks][2] = *(const uint32_t*)(Qhb + (size_t)fr0 * F_ + 16 * ks + 8 + fcc);
        qf[ks][3] = *(const uint32_t*)(Qhb + (size_t)(fr0 + 8) * F_ + 16 * ks + 8 + fcc);
    }

    const int arow = qg * 16 + (lane & 15);
    const int as   = arow & 7;
    const int ah   = lane >> 4;
    const uint32_t qlB = smb + AQL + arow * 512;
    const uint32_t pB  = smb + APS + arow * 128;
    const int brow = ((lane >> 4) << 3) + (lane & 7);
    const int bs   = lane & 7;
    const int bh2  = (lane >> 3) & 1;
    const int crow = qg * 16 + (lane >> 2);
    const int lq   = lane & 3;

    float accO[16][4];
    #pragma unroll
    for (int i = 0; i < 16; i++)
        #pragma unroll
        for (int j = 0; j < 4; j++) accO[i][j] = 0.f;
    float lsum0 = 0.f, lsum1 = 0.f;
    const float scale = 0.0625f;

    for (int it = 0; it < NKT; it++) {
        const int cur = it & 1;
        CP_WAIT0();
        __syncthreads();
        if (it + 1 < NKT) { AISSUE(cur ^ 1, (it + 1) * BKA); CP_COMMIT(); }

        // ---- S = Qh@Kh + Qh@Kl + Ql@Kh : warp 16q x 16k ----
        float sa[2][4];
        #pragma unroll
        for (int j = 0; j < 4; j++) { sa[0][j] = 0.f; sa[1][j] = 0.f; }
        const uint32_t kbH = smb + AKH(cur) + (kh * 16 + brow) * 512;
        const uint32_t kbL = smb + AKL(cur) + (kh * 16 + brow) * 512;
        #pragma unroll
        for (int ks = 0; ks < 16; ks++) {
            uint32_t al4[4], bh4[4], bl4[4];
            uint32_t qc = ((uint32_t)((2 * ks + ah) ^ as)) << 4;
            ldsm4(al4[0], al4[1], al4[2], al4[3], qlB + qc);
            uint32_t kc = ((uint32_t)((2 * ks + bh2) ^ bs)) << 4;
            ldsm4(bh4[0], bh4[1], bh4[2], bh4[3], kbH + kc);
            ldsm4(bl4[0], bl4[1], bl4[2], bl4[3], kbL + kc);
            mma_bf16(sa[0], qf[ks], bh4[0], bh4[1]);
            mma_bf16(sa[0], qf[ks], bl4[0], bl4[1]);
            mma_bf16(sa[0], al4,    bh4[0], bh4[1]);
            mma_bf16(sa[1], qf[ks], bh4[2], bh4[3]);
            mma_bf16(sa[1], qf[ks], bl4[2], bl4[3]);
            mma_bf16(sa[1], al4,    bh4[2], bh4[3]);
        }

        // ---- softmax (no max-sub), split, store P (hi ch0-3 / lo ch4-7) ----
        {
            const int rA = crow, rB = crow + 8;
            #pragma unroll
            for (int nt = 0; nt < 2; nt++) {
                float p0 = __expf(sa[nt][0] * scale);
                float p1 = __expf(sa[nt][1] * scale);
                float p2 = __expf(sa[nt][2] * scale);
                float p3 = __expf(sa[nt][3] * scale);
                lsum0 += p0 + p1;
                lsum1 += p2 + p3;
                int hc = kh * 2 + nt;       // hi chunk 0..3
                uint32_t hA = (uint32_t)(rA * 128 + ((hc ^ (rA & 7)) << 4) + lq * 4);
                uint32_t hB = (uint32_t)(rB * 128 + ((hc ^ (rB & 7)) << 4) + lq * 4);
                uint32_t lA = (uint32_t)(rA * 128 + (((hc + 4) ^ (rA & 7)) << 4) + lq * 4);
                uint32_t lB = (uint32_t)(rB * 128 + (((hc + 4) ^ (rB & 7)) << 4) + lq * 4);
                __nv_bfloat16 h0,l0,h1,l1,h2,l2,h3,l3;
                split_bf16(p0,h0,l0); split_bf16(p1,h1,l1);
                split_bf16(p2,h2,l2); split_bf16(p3,h3,l3);
                *(uint32_t*)(sm + APS + hA) = pack2(h0, h1);
                *(uint32_t*)(sm + APS + hB) = pack2(h2, h3);
                *(uint32_t*)(sm + APS + lA) = pack2(l0, l1);
                *(uint32_t*)(sm + APS + lB) = pack2(l2, l3);
            }
        }
        __syncthreads();

        // ---- O += Ph@Vh + Ph@Vl + Pl@Vh : warp 16q x 128f ----
        {
            uint32_t pf[2][4], plf[2][4];
            #pragma unroll
            for (int ks = 0; ks < 2; ks++) {
                uint32_t hc = (uint32_t)(2 * ks + ah);
                ldsm4(pf[ks][0], pf[ks][1], pf[ks][2], pf[ks][3],
                      pB + ((hc ^ (uint32_t)as) << 4));
                ldsm4(plf[ks][0], plf[ks][1], plf[ks][2], plf[ks][3],
                      pB + (((hc + 4) ^ (uint32_t)as) << 4));
            }
            const uint32_t vb = smb + AV(cur) + (kh * 128 + brow) * 128;
            #pragma unroll
            for (int np = 0; np < 8; np++) {
                #pragma unroll
                for (int ks = 0; ks < 2; ks++) {
                    uint32_t vh4[4], vl4[4];
                    uint32_t ch = (uint32_t)(2 * ks + bh2);
                    uint32_t base = vb + np * 16 * 128;
                    ldsm4(vh4[0], vh4[1], vh4[2], vh4[3],
                          base + ((ch ^ (uint32_t)bs) << 4));
                    ldsm4(vl4[0], vl4[1], vl4[2], vl4[3],
                          base + (((ch + 4) ^ (uint32_t)bs) << 4));
                    const int n0 = np * 2, n1 = np * 2 + 1;
                    mma_bf16(accO[n0], pf[ks],  vh4[0], vh4[1]);
                    mma_bf16(accO[n0], pf[ks],  vl4[0], vl4[1]);
                    mma_bf16(accO[n0], plf[ks], vh4[0], vh4[1]);
                    mma_bf16(accO[n1], pf[ks],  vh4[2], vh4[3]);
                    mma_bf16(accO[n1], pf[ks],  vl4[2], vl4[3]);
                    mma_bf16(accO[n1], plf[ks], vh4[2], vh4[3]);
                }
            }
        }
    }

    // ---- reduce l across kh pairs, normalize, split-bf16 output ----
    float* lsm = (float*)(sm + ALS);
    lsum0 += __shfl_xor_sync(0xffffffffu, lsum0, 1);
    lsum0 += __shfl_xor_sync(0xffffffffu, lsum0, 2);
    lsum1 += __shfl_xor_sync(0xffffffffu, lsum1, 1);
    lsum1 += __shfl_xor_sync(0xffffffffu, lsum1, 2);
    __syncthreads();
    if (lq == 0) {
        lsm[kh * 128 + crow]     = lsum0;
        lsm[kh * 128 + crow + 8] = lsum1;
    }
    __syncthreads();

    const float inv0 = 1.f / (lsm[crow]     + lsm[128 + crow]);
    const float inv1 = 1.f / (lsm[crow + 8] + lsm[128 + crow + 8]);
    const size_t base0 = ((size_t)(b * S1_ + q0 + crow)) * F_;
    const size_t base1 = ((size_t)(b * S1_ + q0 + crow + 8)) * F_;
    #pragma unroll
    for (int nt = 0; nt < 16; nt++) {
        int col = kh * 128 + nt * 8 + 2 * lq;
        __nv_bfloat16 h0,l0,h1,l1,h2,l2,h3,l3;
        split_bf16(accO[nt][0] * inv0, h0, l0);
        split_bf16(accO[nt][1] * inv0, h1, l1);
        split_bf16(accO[nt][2] * inv1, h2, l2);
        split_bf16(accO[nt][3] * inv1, h3, l3);
        *(uint32_t*)(AOh + base0 + col) = pack2(h0, h1);
        *(uint32_t*)(AOl + base0 + col) = pack2(l0, l1);
        *(uint32_t*)(AOh + base1 + col) = pack2(h2, h3);
        *(uint32_t*)(AOl + base1 + col) = pack2(l2, l3);
    }
}

// ---------------------------------------------------------------------------
extern "C" void kernel_launch(void* const* d_in, const int* in_sizes, int n_in,
                              void* d_out, int out_size)
{
    const float* feat1 = (const float*)d_in[0];
    const float* feat2 = (const float*)d_in[1];
    const float* Wq    = (const float*)d_in[2];
    const float* bq    = (const float*)d_in[3];
    const float* Wk    = (const float*)d_in[4];
    const float* bk    = (const float*)d_in[5];
    const float* Wv    = (const float*)d_in[6];
    const float* bv    = (const float*)d_in[7];
    const float* Wfc   = (const float*)d_in[8];
    const float* bfc   = (const float*)d_in[9];
    float* out = (float*)d_out;

    __nv_bfloat16 *f1h, *f1l, *f2h, *f2l, *Qh, *Ql, *Kh, *Kl, *VTh, *VTl, *AOh, *AOl;
    __nv_bfloat16 (*wq)[D_ * F_]; __nv_bfloat16 (*wk)[D_ * F_];
    __nv_bfloat16 (*wv)[D_ * F_]; __nv_bfloat16 (*wf)[F_ * F_];
    cudaGetSymbolAddress((void**)&f1h, g_f1h);
    cudaGetSymbolAddress((void**)&f1l, g_f1l);
    cudaGetSymbolAddress((void**)&f2h, g_f2h);
    cudaGetSymbolAddress((void**)&f2l, g_f2l);
    cudaGetSymbolAddress((void**)&wq,  g_wq);
    cudaGetSymbolAddress((void**)&wk,  g_wk);
    cudaGetSymbolAddress((void**)&wv,  g_wv);
    cudaGetSymbolAddress((void**)&wf,  g_wf);
    cudaGetSymbolAddress((void**)&Qh,  g_Qh);
    cudaGetSymbolAddress((void**)&Ql,  g_Ql);
    cudaGetSymbolAddress((void**)&Kh,  g_Kh);
    cudaGetSymbolAddress((void**)&Kl,  g_Kl);
    cudaGetSymbolAddress((void**)&VTh, g_VTh);
    cudaGetSymbolAddress((void**)&VTl, g_VTl);
    cudaGetSymbolAddress((void**)&AOh, g_AOh);
    cudaGetSymbolAddress((void**)&AOl, g_AOl);

    split_f32_kernel<<<NFEAT / 4 / 256, 256>>>(feat1, f1h, f1l, NFEAT / 4);
    split_f32_kernel<<<NFEAT / 4 / 256, 256>>>(feat2, f2h, f2l, NFEAT / 4);
    split_weights_kernel<<<(3 * D_ * F_ + F_ * F_ + 255) / 256, 256>>>(
        Wq, Wk, Wv, Wfc, wq[0], wq[1], wk[0], wk[1], wv[0], wv[1], wf[0], wf[1]);

    cudaFuncSetAttribute(gemm_qkv, cudaFuncAttributeMaxDynamicSharedMemorySize, GEMM_SMEM);
    cudaFuncSetAttribute(gemm_fc,  cudaFuncAttributeMaxDynamicSharedMemorySize, GEMM_SMEM);
    cudaFuncSetAttribute(attn_kernel, cudaFuncAttributeMaxDynamicSharedMemorySize, ATTN_SMEM);

    dim3 gq(2, B_ * S1_ / 128, 3);   // fused Q/K/V
    gemm_qkv<<<gq, 256, GEMM_SMEM>>>(f1h, f1l, f2h, f2l,
                                     wq[0], wq[1], wk[0], wk[1], wv[0], wv[1],
                                     bq, bk, bv, Qh, Ql, Kh, Kl, VTh, VTl);

    dim3 ag(S1_ / BQA, B_);          // (16, 8) — single wave
    attn_kernel<<<ag, 512, ATTN_SMEM>>>(Qh, Ql, Kh, Kl, VTh, VTl, AOh, AOl);

    dim3 gg(2, B_ * S1_ / 128);
    gemm_fc<<<gg, 256, GEMM_SMEM>>>(AOh, AOl, wf[0], wf[1], bfc, out);
}